// round 4
// baseline (speedup 1.0000x reference)
#include <cuda_runtime.h>
#include <math.h>

#define BATCH   256
#define DIM     768
#define NVOCAB  100000
#define VTOP    80
#define SEC     (BATCH*DIM)   // 196608 floats per output section

// ---------------- device scratch (static globals; no allocation) ----------------
__device__ float g_inv_norm[NVOCAB];
__device__ float g_x[BATCH*3072];
__device__ float g_h1[BATCH*2304];
__device__ float g_h2[BATCH*1700];
__device__ float g_h3[BATCH*1000];
__device__ float g_raw4[BATCH*DIM];
__device__ float g_model[BATCH*DIM];
__device__ float g_sims[BATCH*NVOCAB];          // ~102 MB
__device__ int   g_topk[BATCH*VTOP];
__device__ float g_word[BATCH*VTOP*DIM];        // ~63 MB
__device__ float g_board[BATCH*26*DIM];         // ~20 MB

__device__ __forceinline__ float warp_sum(float v) {
#pragma unroll
    for (int o = 16; o; o >>= 1) v += __shfl_xor_sync(0xffffffffu, v, o);
    return v;
}

// ---------------- vocab inverse norms ----------------
__global__ __launch_bounds__(256) void vocab_norms(const float* __restrict__ vocab, int NV) {
    int row = blockIdx.x * 8 + (threadIdx.x >> 5);
    int lane = threadIdx.x & 31;
    if (row >= NV) return;
    const float* src = vocab + (size_t)row * DIM;
    float s = 0.f;
#pragma unroll 4
    for (int d = lane; d < DIM; d += 32) { float v = src[d]; s += v * v; }
    s = warp_sum(s);
    if (lane == 0) g_inv_norm[row] = 1.0f / fmaxf(sqrtf(s), 1e-12f);
}

// ---------------- board prep: normalized words + pooled MLP input ----------------
__global__ __launch_bounds__(256) void board_prep(
    const float* __restrict__ pos, const float* __restrict__ neg,
    const float* __restrict__ neut, const float* __restrict__ assas)
{
    int b = blockIdx.x;
    int t = threadIdx.x;
    int warp = t >> 5, lane = t & 31;

    // --- per-word L2-normalized embeddings into g_board, order: pos(0-8) neg(9-17) neut(18-24) assas(25)
    for (int w = warp; w < 26; w += 8) {
        const float* src;
        if (w < 9)       src = pos  + ((size_t)b * 9 + w) * DIM;
        else if (w < 18) src = neg  + ((size_t)b * 9 + (w - 9)) * DIM;
        else if (w < 25) src = neut + ((size_t)b * 7 + (w - 18)) * DIM;
        else             src = assas + (size_t)b * DIM;
        float s = 0.f;
        for (int d = lane; d < DIM; d += 32) { float v = src[d]; s += v * v; }
        s = warp_sum(s);
        float inv = 1.0f / fmaxf(sqrtf(s), 1e-8f);
        float* dst = g_board + ((size_t)b * 26 + w) * DIM;
        for (int d = lane; d < DIM; d += 32) dst[d] = src[d] * inv;
    }

    // --- pooled groups -> g_x[b, 3072]: [neg_pool | assassin_raw | neut_pool | pos_pool]
    __shared__ float red[256];
    float* xb = g_x + (size_t)b * 3072;

    // assassin raw copy
#pragma unroll
    for (int r = 0; r < 3; r++) {
        int d = t + 256 * r;
        xb[768 + d] = assas[(size_t)b * DIM + d];
    }

    const float* srcs[3] = { neg, neut, pos };
    const int nw[3] = { 9, 7, 9 };
    const int xoff[3] = { 0, 1536, 2304 };
    for (int g = 0; g < 3; g++) {
        float m[3];
#pragma unroll
        for (int r = 0; r < 3; r++) {
            int d = t + 256 * r;
            float s = 0.f;
            for (int w = 0; w < nw[g]; w++)
                s += srcs[g][((size_t)b * nw[g] + w) * DIM + d];
            m[r] = s / (float)nw[g];
        }
        red[t] = m[0]*m[0] + m[1]*m[1] + m[2]*m[2];
        __syncthreads();
        for (int s = 128; s > 0; s >>= 1) { if (t < s) red[t] += red[t + s]; __syncthreads(); }
        float inv = 1.0f / fmaxf(sqrtf(red[0]), 1e-12f);
        __syncthreads();
#pragma unroll
        for (int r = 0; r < 3; r++) xb[xoff[g] + t + 256 * r] = m[r] * inv;
    }
}

// ---------------- generic 128x128x8 SGEMM ----------------
// BT=false: C[M,N] = A[M,K] @ B[K,N]   (B row-major [K,N])
// BT=true:  C[M,N] = A[M,K] @ B^T      (B row-major [N,K])
// mode 0: +bias(aux[n]); mode 1: +bias, relu; mode 2: *aux[n] (scale)
template<bool BT>
__global__ __launch_bounds__(256) void sgemm128(
    const float* __restrict__ A, const float* __restrict__ B,
    const float* __restrict__ aux, float* __restrict__ C,
    int M, int N, int K, int mode)
{
    __shared__ float As[8][128];
    __shared__ float Bs[8][128];
    int tid = threadIdx.x;
    int m0 = blockIdx.y * 128, n0 = blockIdx.x * 128;
    int tx = tid & 15, ty = tid >> 4;

    float acc[8][8];
#pragma unroll
    for (int i = 0; i < 8; i++)
#pragma unroll
        for (int j = 0; j < 8; j++) acc[i][j] = 0.f;

    int lr = tid >> 1;            // 0..127
    int lc = (tid & 1) * 4;       // 0 or 4
    int bnr = tid >> 5;           // 0..7 (k row) for NN B
    int bnc = (tid & 31) * 4;     // n offset for NN B

    for (int k0 = 0; k0 < K; k0 += 8) {
        float4 av = make_float4(0.f, 0.f, 0.f, 0.f);
        {
            int gm = m0 + lr, gk = k0 + lc;
            if (gm < M && gk < K) av = *(const float4*)(A + (size_t)gm * K + gk);
        }
        As[lc + 0][lr] = av.x; As[lc + 1][lr] = av.y;
        As[lc + 2][lr] = av.z; As[lc + 3][lr] = av.w;

        if (BT) {
            float4 bv = make_float4(0.f, 0.f, 0.f, 0.f);
            int gn = n0 + lr, gk = k0 + lc;
            if (gn < N && gk < K) bv = *(const float4*)(B + (size_t)gn * K + gk);
            Bs[lc + 0][lr] = bv.x; Bs[lc + 1][lr] = bv.y;
            Bs[lc + 2][lr] = bv.z; Bs[lc + 3][lr] = bv.w;
        } else {
            float4 bv = make_float4(0.f, 0.f, 0.f, 0.f);
            int gk = k0 + bnr, gn = n0 + bnc;
            if (gk < K && gn < N) bv = *(const float4*)(B + (size_t)gk * N + gn);
            *(float4*)&Bs[bnr][bnc] = bv;
        }
        __syncthreads();

#pragma unroll
        for (int kk = 0; kk < 8; kk++) {
            float4 a0 = *(const float4*)&As[kk][ty * 8];
            float4 a1 = *(const float4*)&As[kk][ty * 8 + 4];
            float4 b0 = *(const float4*)&Bs[kk][tx * 8];
            float4 b1 = *(const float4*)&Bs[kk][tx * 8 + 4];
            float ar[8] = { a0.x, a0.y, a0.z, a0.w, a1.x, a1.y, a1.z, a1.w };
            float br[8] = { b0.x, b0.y, b0.z, b0.w, b1.x, b1.y, b1.z, b1.w };
#pragma unroll
            for (int i = 0; i < 8; i++)
#pragma unroll
                for (int j = 0; j < 8; j++)
                    acc[i][j] += ar[i] * br[j];
        }
        __syncthreads();
    }

#pragma unroll
    for (int i = 0; i < 8; i++) {
        int gm = m0 + ty * 8 + i;
        if (gm >= M) continue;
#pragma unroll
        for (int j = 0; j < 8; j++) {
            int gn = n0 + tx * 8 + j;
            if (gn >= N) continue;
            float v = acc[i][j];
            if (mode == 2) v *= aux[gn];
            else { v += aux[gn]; if (mode == 1) v = fmaxf(v, 0.f); }
            C[(size_t)gm * N + gn] = v;
        }
    }
}

// ---------------- row L2 normalize of raw layer-4 output -> g_model and out[sec0] ----------------
__global__ __launch_bounds__(256) void norm_rows(float* __restrict__ out) {
    int b = blockIdx.x, t = threadIdx.x;
    __shared__ float red[256];
    const float* in = g_raw4 + (size_t)b * DIM;
    float v0 = in[t], v1 = in[t + 256], v2 = in[t + 512];
    red[t] = v0 * v0 + v1 * v1 + v2 * v2;
    __syncthreads();
    for (int s = 128; s > 0; s >>= 1) { if (t < s) red[t] += red[t + s]; __syncthreads(); }
    float inv = 1.0f / fmaxf(sqrtf(red[0]), 1e-12f);
    float* gm = g_model + (size_t)b * DIM;
    float* om = out + (size_t)b * DIM;
    gm[t] = v0 * inv;        om[t] = v0 * inv;
    gm[t + 256] = v1 * inv;  om[t + 256] = v1 * inv;
    gm[t + 512] = v2 * inv;  om[t + 512] = v2 * inv;
}

// ---------------- top-80 per row: histogram threshold + exact rank select ----------------
__global__ __launch_bounds__(256) void topk_kernel(int NV) {
    __shared__ unsigned int hist[2048];
    __shared__ float cval[2048];
    __shared__ int   cidx[2048];
    __shared__ int s_cnt, s_thr;
    int b = blockIdx.x, t = threadIdx.x;
    for (int i = t; i < 2048; i += 256) hist[i] = 0;
    if (t == 0) s_cnt = 0;
    __syncthreads();

    const float* row = g_sims + (size_t)b * NV;
    for (int n = t; n < NV; n += 256) {
        float v = row[n];
        int bin = (int)((v + 1.0f) * 1024.0f);
        bin = min(max(bin, 0), 2047);
        atomicAdd(&hist[bin], 1u);
    }
    __syncthreads();
    if (t == 0) {
        unsigned int c = 0; int bin = 2047;
        for (; bin >= 0; bin--) { c += hist[bin]; if (c >= VTOP) break; }
        s_thr = bin;
    }
    __syncthreads();
    int thr = s_thr;
    for (int n = t; n < NV; n += 256) {
        float v = row[n];
        int bin = (int)((v + 1.0f) * 1024.0f);
        bin = min(max(bin, 0), 2047);
        if (bin >= thr) {
            int p = atomicAdd(&s_cnt, 1);
            if (p < 2048) { cval[p] = v; cidx[p] = n; }
        }
    }
    __syncthreads();
    int C = min(s_cnt, 2048);
    // exact rank with lax.top_k tie-break: value desc, index asc
    for (int i = t; i < C; i += 256) {
        float vi = cval[i]; int ii = cidx[i];
        int r = 0;
        for (int j = 0; j < C; j++) {
            float vj = cval[j];
            r += (vj > vi) || (vj == vi && cidx[j] < ii);
        }
        if (r < VTOP) g_topk[b * VTOP + r] = ii;
    }
}

// ---------------- gather normalized word embeddings; write out[sec1] for v==0 ----------------
__global__ __launch_bounds__(256) void gather_kernel(const float* __restrict__ vocab, float* __restrict__ out) {
    int v = blockIdx.x, b = blockIdx.y, t = threadIdx.x;
    int idx = g_topk[b * VTOP + v];
    float inv = g_inv_norm[idx];
    const float* src = vocab + (size_t)idx * DIM;
    float* dst = g_word + ((size_t)b * VTOP + v) * DIM;
    for (int d = t; d < DIM; d += 256) {
        float val = src[d] * inv;
        dst[d] = val;
        if (v == 0) out[SEC + (size_t)b * DIM + d] = val;
    }
}

// ---------------- scoring + reward + selection + pooling ----------------
__global__ __launch_bounds__(256) void score_kernel(float* __restrict__ out) {
    int b = blockIdx.x, t = threadIdx.x;
    int warp = t >> 5, lane = t & 31;
    __shared__ float S[VTOP][26];
    __shared__ float tot[VTOP];
    __shared__ unsigned char inmax[VTOP], inmin[VTOP];
    __shared__ float red[256];

    // Phase A: cosine scores S[v][j] = word_v . board_j (both unit vectors)
    for (int v = warp; v < VTOP; v += 8) {
        if (lane < 26) {
            const float4* w = (const float4*)(g_word + ((size_t)b * VTOP + v) * DIM);
            const float4* brd = (const float4*)(g_board + ((size_t)b * 26 + lane) * DIM);
            float acc = 0.f;
#pragma unroll 8
            for (int d = 0; d < DIM / 4; d++) {
                float4 a = w[d], c = brd[d];
                acc += a.x * c.x + a.y * c.y + a.z * c.z + a.w * c.w;
            }
            S[v][lane] = acc;
        }
    }
    __syncthreads();

    // Phase B: num_correct, secondary reward, tot (exact small floats)
    if (t < VTOP) {
        float maxbad = -1e30f;
#pragma unroll
        for (int j = 9; j < 26; j++) maxbad = fmaxf(maxbad, S[t][j]);
        int nc = 0;
#pragma unroll
        for (int j = 0; j < 9; j++) nc += (S[t][j] >= maxbad) ? 1 : 0;
        int jm = 25;
        for (int j = 9; j < 26; j++) { if (S[t][j] == maxbad) { jm = j; break; } }
        float sec = (jm <= 17) ? 0.0f : ((jm <= 24) ? 1.0f : -10.0f);
        tot[t] = (float)nc + sec;
    }
    __syncthreads();

    // Phase C: top-40 / bottom-40 selection with stable tie-break (lower index first)
    if (t < VTOP) {
        float tv = tot[t];
        int rmax = 0, rmin = 0;
        for (int u = 0; u < VTOP; u++) {
            float tu = tot[u];
            rmax += (tu > tv) || (tu == tv && u < t);
            rmin += (tu < tv) || (tu == tv && u < t);
        }
        inmax[t] = (rmax < VTOP / 2);
        inmin[t] = (rmin < VTOP / 2);
    }
    __syncthreads();

    // Phase D: pool selected embeddings -> mean -> normalize -> out[sec2], out[sec3]
    float smax[3] = {0.f, 0.f, 0.f}, smin[3] = {0.f, 0.f, 0.f};
    for (int v = 0; v < VTOP; v++) {
        const float* w = g_word + ((size_t)b * VTOP + v) * DIM;
        bool fx = inmax[v], fn = inmin[v];
#pragma unroll
        for (int r = 0; r < 3; r++) {
            float val = w[t + 256 * r];
            if (fx) smax[r] += val;
            if (fn) smin[r] += val;
        }
    }
#pragma unroll
    for (int r = 0; r < 3; r++) { smax[r] *= (1.0f / 40.0f); smin[r] *= (1.0f / 40.0f); }

    red[t] = smax[0]*smax[0] + smax[1]*smax[1] + smax[2]*smax[2];
    __syncthreads();
    for (int s = 128; s > 0; s >>= 1) { if (t < s) red[t] += red[t + s]; __syncthreads(); }
    float invx = 1.0f / fmaxf(sqrtf(red[0]), 1e-12f);
    __syncthreads();
#pragma unroll
    for (int r = 0; r < 3; r++) out[2 * SEC + (size_t)b * DIM + t + 256 * r] = smax[r] * invx;

    red[t] = smin[0]*smin[0] + smin[1]*smin[1] + smin[2]*smin[2];
    __syncthreads();
    for (int s = 128; s > 0; s >>= 1) { if (t < s) red[t] += red[t + s]; __syncthreads(); }
    float invn = 1.0f / fmaxf(sqrtf(red[0]), 1e-12f);
    __syncthreads();
#pragma unroll
    for (int r = 0; r < 3; r++) out[3 * SEC + (size_t)b * DIM + t + 256 * r] = smin[r] * invn;
}

// ---------------- launch ----------------
extern "C" void kernel_launch(void* const* d_in, const int* in_sizes, int n_in,
                              void* d_out, int out_size)
{
    const float* pos   = (const float*)d_in[0];
    const float* neg   = (const float*)d_in[1];
    const float* neut  = (const float*)d_in[2];
    const float* assas = (const float*)d_in[3];
    const float* vocab = (const float*)d_in[4];
    const float* W1 = (const float*)d_in[5];  const float* b1 = (const float*)d_in[6];
    const float* W2 = (const float*)d_in[7];  const float* b2 = (const float*)d_in[8];
    const float* W3 = (const float*)d_in[9];  const float* b3 = (const float*)d_in[10];
    const float* W4 = (const float*)d_in[11]; const float* b4 = (const float*)d_in[12];
    float* out = (float*)d_out;
    int NV = in_sizes[4] / DIM;

    float *p_x, *p_h1, *p_h2, *p_h3, *p_raw4, *p_model, *p_sims, *p_inv;
    cudaGetSymbolAddress((void**)&p_x,     g_x);
    cudaGetSymbolAddress((void**)&p_h1,    g_h1);
    cudaGetSymbolAddress((void**)&p_h2,    g_h2);
    cudaGetSymbolAddress((void**)&p_h3,    g_h3);
    cudaGetSymbolAddress((void**)&p_raw4,  g_raw4);
    cudaGetSymbolAddress((void**)&p_model, g_model);
    cudaGetSymbolAddress((void**)&p_sims,  g_sims);
    cudaGetSymbolAddress((void**)&p_inv,   g_inv_norm);

    vocab_norms<<<(NV + 7) / 8, 256>>>(vocab, NV);
    board_prep<<<BATCH, 256>>>(pos, neg, neut, assas);

    dim3 g1((2304 + 127) / 128, 2);
    sgemm128<false><<<g1, 256>>>(p_x,  W1, b1, p_h1,   BATCH, 2304, 3072, 1);
    dim3 g2((1700 + 127) / 128, 2);
    sgemm128<false><<<g2, 256>>>(p_h1, W2, b2, p_h2,   BATCH, 1700, 2304, 1);
    dim3 g3((1000 + 127) / 128, 2);
    sgemm128<false><<<g3, 256>>>(p_h2, W3, b3, p_h3,   BATCH, 1000, 1700, 1);
    dim3 g4((768 + 127) / 128, 2);
    sgemm128<false><<<g4, 256>>>(p_h3, W4, b4, p_raw4, BATCH, 768, 1000, 0);

    norm_rows<<<BATCH, 256>>>(out);

    dim3 gs((NV + 127) / 128, 2);
    sgemm128<true><<<gs, 256>>>(p_model, vocab, p_inv, p_sims, BATCH, NV, DIM, 2);

    topk_kernel<<<BATCH, 256>>>(NV);
    gather_kernel<<<dim3(VTOP, BATCH), 256>>>(vocab, out);
    score_kernel<<<BATCH, 256>>>(out);
}

// round 5
// speedup vs baseline: 1.0088x; 1.0088x over previous
#include <cuda_runtime.h>
#include <math.h>

#define BATCH   256
#define DIM     768
#define NVOCAB  100000
#define VTOP    80
#define SEC     (BATCH*DIM)   // 196608 floats per output section

// ---------------- device scratch (static globals; no allocation) ----------------
__device__ float g_inv_norm[NVOCAB];
__device__ float g_x[BATCH*3072];
__device__ float g_h1[BATCH*2304];
__device__ float g_h2[BATCH*1700];
__device__ float g_h3[BATCH*1000];
__device__ float g_raw4[BATCH*DIM];
__device__ float g_model[BATCH*DIM];
__device__ float g_sims[BATCH*NVOCAB];          // ~102 MB
__device__ int   g_topk[BATCH*VTOP];
__device__ float g_word[BATCH*VTOP*DIM];        // ~63 MB
__device__ float g_board[BATCH*26*DIM];         // ~20 MB

__device__ __forceinline__ float warp_sum(float v) {
#pragma unroll
    for (int o = 16; o; o >>= 1) v += __shfl_xor_sync(0xffffffffu, v, o);
    return v;
}

// ---------------- vocab inverse norms ----------------
__global__ __launch_bounds__(256) void vocab_norms(const float* __restrict__ vocab, int NV) {
    int row = blockIdx.x * 8 + (threadIdx.x >> 5);
    int lane = threadIdx.x & 31;
    if (row >= NV) return;
    const float* src = vocab + (size_t)row * DIM;
    float s = 0.f;
#pragma unroll 4
    for (int d = lane; d < DIM; d += 32) { float v = src[d]; s += v * v; }
    s = warp_sum(s);
    if (lane == 0) g_inv_norm[row] = 1.0f / fmaxf(sqrtf(s), 1e-12f);
}

// ---------------- board prep: normalized words + pooled MLP input ----------------
__global__ __launch_bounds__(256) void board_prep(
    const float* __restrict__ pos, const float* __restrict__ neg,
    const float* __restrict__ neut, const float* __restrict__ assas)
{
    int b = blockIdx.x;
    int t = threadIdx.x;
    int warp = t >> 5, lane = t & 31;

    // --- per-word L2-normalized embeddings into g_board, order: pos(0-8) neg(9-17) neut(18-24) assas(25)
    for (int w = warp; w < 26; w += 8) {
        const float* src;
        if (w < 9)       src = pos  + ((size_t)b * 9 + w) * DIM;
        else if (w < 18) src = neg  + ((size_t)b * 9 + (w - 9)) * DIM;
        else if (w < 25) src = neut + ((size_t)b * 7 + (w - 18)) * DIM;
        else             src = assas + (size_t)b * DIM;
        float s = 0.f;
        for (int d = lane; d < DIM; d += 32) { float v = src[d]; s += v * v; }
        s = warp_sum(s);
        float inv = 1.0f / fmaxf(sqrtf(s), 1e-8f);
        float* dst = g_board + ((size_t)b * 26 + w) * DIM;
        for (int d = lane; d < DIM; d += 32) dst[d] = src[d] * inv;
    }

    // --- pooled groups -> g_x[b, 3072]: [neg_pool | assassin_raw | neut_pool | pos_pool]
    __shared__ float red[256];
    float* xb = g_x + (size_t)b * 3072;

    // assassin raw copy
#pragma unroll
    for (int r = 0; r < 3; r++) {
        int d = t + 256 * r;
        xb[768 + d] = assas[(size_t)b * DIM + d];
    }

    const float* srcs[3] = { neg, neut, pos };
    const int nw[3] = { 9, 7, 9 };
    const int xoff[3] = { 0, 1536, 2304 };
    for (int g = 0; g < 3; g++) {
        float m[3];
#pragma unroll
        for (int r = 0; r < 3; r++) {
            int d = t + 256 * r;
            float s = 0.f;
            for (int w = 0; w < nw[g]; w++)
                s += srcs[g][((size_t)b * nw[g] + w) * DIM + d];
            m[r] = s / (float)nw[g];
        }
        red[t] = m[0]*m[0] + m[1]*m[1] + m[2]*m[2];
        __syncthreads();
        for (int s = 128; s > 0; s >>= 1) { if (t < s) red[t] += red[t + s]; __syncthreads(); }
        float inv = 1.0f / fmaxf(sqrtf(red[0]), 1e-12f);
        __syncthreads();
#pragma unroll
        for (int r = 0; r < 3; r++) xb[xoff[g] + t + 256 * r] = m[r] * inv;
    }
}

// ---------------- generic 128x128x8 SGEMM ----------------
// BT=false: C[M,N] = A[M,K] @ B[K,N]   (B row-major [K,N])
// BT=true:  C[M,N] = A[M,K] @ B^T      (B row-major [N,K])
// mode 0: +bias(aux[n]); mode 1: +bias, relu; mode 2: *aux[n] (scale)
template<bool BT>
__global__ __launch_bounds__(256) void sgemm128(
    const float* __restrict__ A, const float* __restrict__ B,
    const float* __restrict__ aux, float* __restrict__ C,
    int M, int N, int K, int mode)
{
    __shared__ float As[8][128];
    __shared__ float Bs[8][128];
    int tid = threadIdx.x;
    int m0 = blockIdx.y * 128, n0 = blockIdx.x * 128;
    int tx = tid & 15, ty = tid >> 4;

    float acc[8][8];
#pragma unroll
    for (int i = 0; i < 8; i++)
#pragma unroll
        for (int j = 0; j < 8; j++) acc[i][j] = 0.f;

    int lr = tid >> 1;            // 0..127
    int lc = (tid & 1) * 4;       // 0 or 4
    int bnr = tid >> 5;           // 0..7 (k row) for NN B
    int bnc = (tid & 31) * 4;     // n offset for NN B

    for (int k0 = 0; k0 < K; k0 += 8) {
        float4 av = make_float4(0.f, 0.f, 0.f, 0.f);
        {
            int gm = m0 + lr, gk = k0 + lc;
            if (gm < M && gk < K) av = *(const float4*)(A + (size_t)gm * K + gk);
        }
        As[lc + 0][lr] = av.x; As[lc + 1][lr] = av.y;
        As[lc + 2][lr] = av.z; As[lc + 3][lr] = av.w;

        if (BT) {
            float4 bv = make_float4(0.f, 0.f, 0.f, 0.f);
            int gn = n0 + lr, gk = k0 + lc;
            if (gn < N && gk < K) bv = *(const float4*)(B + (size_t)gn * K + gk);
            Bs[lc + 0][lr] = bv.x; Bs[lc + 1][lr] = bv.y;
            Bs[lc + 2][lr] = bv.z; Bs[lc + 3][lr] = bv.w;
        } else {
            float4 bv = make_float4(0.f, 0.f, 0.f, 0.f);
            int gk = k0 + bnr, gn = n0 + bnc;
            if (gk < K && gn < N) bv = *(const float4*)(B + (size_t)gk * N + gn);
            *(float4*)&Bs[bnr][bnc] = bv;
        }
        __syncthreads();

#pragma unroll
        for (int kk = 0; kk < 8; kk++) {
            float4 a0 = *(const float4*)&As[kk][ty * 8];
            float4 a1 = *(const float4*)&As[kk][ty * 8 + 4];
            float4 b0 = *(const float4*)&Bs[kk][tx * 8];
            float4 b1 = *(const float4*)&Bs[kk][tx * 8 + 4];
            float ar[8] = { a0.x, a0.y, a0.z, a0.w, a1.x, a1.y, a1.z, a1.w };
            float br[8] = { b0.x, b0.y, b0.z, b0.w, b1.x, b1.y, b1.z, b1.w };
#pragma unroll
            for (int i = 0; i < 8; i++)
#pragma unroll
                for (int j = 0; j < 8; j++)
                    acc[i][j] += ar[i] * br[j];
        }
        __syncthreads();
    }

#pragma unroll
    for (int i = 0; i < 8; i++) {
        int gm = m0 + ty * 8 + i;
        if (gm >= M) continue;
#pragma unroll
        for (int j = 0; j < 8; j++) {
            int gn = n0 + tx * 8 + j;
            if (gn >= N) continue;
            float v = acc[i][j];
            if (mode == 2) v *= aux[gn];
            else { v += aux[gn]; if (mode == 1) v = fmaxf(v, 0.f); }
            C[(size_t)gm * N + gn] = v;
        }
    }
}

// ---------------- row L2 normalize of raw layer-4 output -> g_model and out[sec0] ----------------
__global__ __launch_bounds__(256) void norm_rows(float* __restrict__ out) {
    int b = blockIdx.x, t = threadIdx.x;
    __shared__ float red[256];
    const float* in = g_raw4 + (size_t)b * DIM;
    float v0 = in[t], v1 = in[t + 256], v2 = in[t + 512];
    red[t] = v0 * v0 + v1 * v1 + v2 * v2;
    __syncthreads();
    for (int s = 128; s > 0; s >>= 1) { if (t < s) red[t] += red[t + s]; __syncthreads(); }
    float inv = 1.0f / fmaxf(sqrtf(red[0]), 1e-12f);
    float* gm = g_model + (size_t)b * DIM;
    float* om = out + (size_t)b * DIM;
    gm[t] = v0 * inv;        om[t] = v0 * inv;
    gm[t + 256] = v1 * inv;  om[t + 256] = v1 * inv;
    gm[t + 512] = v2 * inv;  om[t + 512] = v2 * inv;
}

// ---------------- top-80 per row: histogram threshold + exact rank select ----------------
__global__ __launch_bounds__(256) void topk_kernel(int NV) {
    __shared__ unsigned int hist[2048];
    __shared__ float cval[2048];
    __shared__ int   cidx[2048];
    __shared__ int s_cnt, s_thr;
    int b = blockIdx.x, t = threadIdx.x;
    for (int i = t; i < 2048; i += 256) hist[i] = 0;
    if (t == 0) s_cnt = 0;
    __syncthreads();

    const float* row = g_sims + (size_t)b * NV;
    for (int n = t; n < NV; n += 256) {
        float v = row[n];
        int bin = (int)((v + 1.0f) * 1024.0f);
        bin = min(max(bin, 0), 2047);
        atomicAdd(&hist[bin], 1u);
    }
    __syncthreads();
    if (t == 0) {
        unsigned int c = 0; int bin = 2047;
        for (; bin >= 0; bin--) { c += hist[bin]; if (c >= VTOP) break; }
        s_thr = bin;
    }
    __syncthreads();
    int thr = s_thr;
    for (int n = t; n < NV; n += 256) {
        float v = row[n];
        int bin = (int)((v + 1.0f) * 1024.0f);
        bin = min(max(bin, 0), 2047);
        if (bin >= thr) {
            int p = atomicAdd(&s_cnt, 1);
            if (p < 2048) { cval[p] = v; cidx[p] = n; }
        }
    }
    __syncthreads();
    int C = min(s_cnt, 2048);
    // exact rank with lax.top_k tie-break: value desc, index asc
    for (int i = t; i < C; i += 256) {
        float vi = cval[i]; int ii = cidx[i];
        int r = 0;
        for (int j = 0; j < C; j++) {
            float vj = cval[j];
            r += (vj > vi) || (vj == vi && cidx[j] < ii);
        }
        if (r < VTOP) g_topk[b * VTOP + r] = ii;
    }
}

// ---------------- gather normalized word embeddings; write out[sec1] for v==0 ----------------
__global__ __launch_bounds__(256) void gather_kernel(const float* __restrict__ vocab, float* __restrict__ out) {
    int v = blockIdx.x, b = blockIdx.y, t = threadIdx.x;
    int idx = g_topk[b * VTOP + v];
    float inv = g_inv_norm[idx];
    const float* src = vocab + (size_t)idx * DIM;
    float* dst = g_word + ((size_t)b * VTOP + v) * DIM;
    for (int d = t; d < DIM; d += 256) {
        float val = src[d] * inv;
        dst[d] = val;
        if (v == 0) out[SEC + (size_t)b * DIM + d] = val;
    }
}

// ---------------- scoring + reward + selection + pooling ----------------
__global__ __launch_bounds__(256) void score_kernel(float* __restrict__ out) {
    int b = blockIdx.x, t = threadIdx.x;
    int warp = t >> 5, lane = t & 31;
    __shared__ float S[VTOP][26];
    __shared__ float tot[VTOP];
    __shared__ unsigned char inmax[VTOP], inmin[VTOP];
    __shared__ float red[256];

    // Phase A: cosine scores S[v][j] = word_v . board_j (both unit vectors)
    for (int v = warp; v < VTOP; v += 8) {
        if (lane < 26) {
            const float4* w = (const float4*)(g_word + ((size_t)b * VTOP + v) * DIM);
            const float4* brd = (const float4*)(g_board + ((size_t)b * 26 + lane) * DIM);
            float acc = 0.f;
#pragma unroll 8
            for (int d = 0; d < DIM / 4; d++) {
                float4 a = w[d], c = brd[d];
                acc += a.x * c.x + a.y * c.y + a.z * c.z + a.w * c.w;
            }
            S[v][lane] = acc;
        }
    }
    __syncthreads();

    // Phase B: num_correct, secondary reward, tot (exact small floats)
    if (t < VTOP) {
        float maxbad = -1e30f;
#pragma unroll
        for (int j = 9; j < 26; j++) maxbad = fmaxf(maxbad, S[t][j]);
        int nc = 0;
#pragma unroll
        for (int j = 0; j < 9; j++) nc += (S[t][j] >= maxbad) ? 1 : 0;
        int jm = 25;
        for (int j = 9; j < 26; j++) { if (S[t][j] == maxbad) { jm = j; break; } }
        float sec = (jm <= 17) ? 0.0f : ((jm <= 24) ? 1.0f : -10.0f);
        tot[t] = (float)nc + sec;
    }
    __syncthreads();

    // Phase C: top-40 / bottom-40 selection with stable tie-break (lower index first)
    if (t < VTOP) {
        float tv = tot[t];
        int rmax = 0, rmin = 0;
        for (int u = 0; u < VTOP; u++) {
            float tu = tot[u];
            rmax += (tu > tv) || (tu == tv && u < t);
            rmin += (tu < tv) || (tu == tv && u < t);
        }
        inmax[t] = (rmax < VTOP / 2);
        inmin[t] = (rmin < VTOP / 2);
    }
    __syncthreads();

    // Phase D: pool selected embeddings -> mean -> normalize -> out[sec2], out[sec3]
    float smax[3] = {0.f, 0.f, 0.f}, smin[3] = {0.f, 0.f, 0.f};
    for (int v = 0; v < VTOP; v++) {
        const float* w = g_word + ((size_t)b * VTOP + v) * DIM;
        bool fx = inmax[v], fn = inmin[v];
#pragma unroll
        for (int r = 0; r < 3; r++) {
            float val = w[t + 256 * r];
            if (fx) smax[r] += val;
            if (fn) smin[r] += val;
        }
    }
#pragma unroll
    for (int r = 0; r < 3; r++) { smax[r] *= (1.0f / 40.0f); smin[r] *= (1.0f / 40.0f); }

    red[t] = smax[0]*smax[0] + smax[1]*smax[1] + smax[2]*smax[2];
    __syncthreads();
    for (int s = 128; s > 0; s >>= 1) { if (t < s) red[t] += red[t + s]; __syncthreads(); }
    float invx = 1.0f / fmaxf(sqrtf(red[0]), 1e-12f);
    __syncthreads();
#pragma unroll
    for (int r = 0; r < 3; r++) out[2 * SEC + (size_t)b * DIM + t + 256 * r] = smax[r] * invx;

    red[t] = smin[0]*smin[0] + smin[1]*smin[1] + smin[2]*smin[2];
    __syncthreads();
    for (int s = 128; s > 0; s >>= 1) { if (t < s) red[t] += red[t + s]; __syncthreads(); }
    float invn = 1.0f / fmaxf(sqrtf(red[0]), 1e-12f);
    __syncthreads();
#pragma unroll
    for (int r = 0; r < 3; r++) out[3 * SEC + (size_t)b * DIM + t + 256 * r] = smin[r] * invn;
}

// ---------------- launch ----------------
extern "C" void kernel_launch(void* const* d_in, const int* in_sizes, int n_in,
                              void* d_out, int out_size)
{
    const float* pos   = (const float*)d_in[0];
    const float* neg   = (const float*)d_in[1];
    const float* neut  = (const float*)d_in[2];
    const float* assas = (const float*)d_in[3];
    const float* vocab = (const float*)d_in[4];
    const float* W1 = (const float*)d_in[5];  const float* b1 = (const float*)d_in[6];
    const float* W2 = (const float*)d_in[7];  const float* b2 = (const float*)d_in[8];
    const float* W3 = (const float*)d_in[9];  const float* b3 = (const float*)d_in[10];
    const float* W4 = (const float*)d_in[11]; const float* b4 = (const float*)d_in[12];
    float* out = (float*)d_out;
    int NV = in_sizes[4] / DIM;

    float *p_x, *p_h1, *p_h2, *p_h3, *p_raw4, *p_model, *p_sims, *p_inv;
    cudaGetSymbolAddress((void**)&p_x,     g_x);
    cudaGetSymbolAddress((void**)&p_h1,    g_h1);
    cudaGetSymbolAddress((void**)&p_h2,    g_h2);
    cudaGetSymbolAddress((void**)&p_h3,    g_h3);
    cudaGetSymbolAddress((void**)&p_raw4,  g_raw4);
    cudaGetSymbolAddress((void**)&p_model, g_model);
    cudaGetSymbolAddress((void**)&p_sims,  g_sims);
    cudaGetSymbolAddress((void**)&p_inv,   g_inv_norm);

    vocab_norms<<<(NV + 7) / 8, 256>>>(vocab, NV);
    board_prep<<<BATCH, 256>>>(pos, neg, neut, assas);

    dim3 g1((2304 + 127) / 128, 2);
    sgemm128<false><<<g1, 256>>>(p_x,  W1, b1, p_h1,   BATCH, 2304, 3072, 1);
    dim3 g2((1700 + 127) / 128, 2);
    sgemm128<false><<<g2, 256>>>(p_h1, W2, b2, p_h2,   BATCH, 1700, 2304, 1);
    dim3 g3((1000 + 127) / 128, 2);
    sgemm128<false><<<g3, 256>>>(p_h2, W3, b3, p_h3,   BATCH, 1000, 1700, 1);
    dim3 g4((768 + 127) / 128, 2);
    sgemm128<false><<<g4, 256>>>(p_h3, W4, b4, p_raw4, BATCH, 768, 1000, 0);

    norm_rows<<<BATCH, 256>>>(out);

    dim3 gs((NV + 127) / 128, 2);
    sgemm128<true><<<gs, 256>>>(p_model, vocab, p_inv, p_sims, BATCH, NV, DIM, 2);

    topk_kernel<<<BATCH, 256>>>(NV);
    gather_kernel<<<dim3(VTOP, BATCH), 256>>>(vocab, out);
    score_kernel<<<BATCH, 256>>>(out);
}

// round 6
// speedup vs baseline: 1.0126x; 1.0038x over previous
#include <cuda_runtime.h>
#include <math.h>

#define BATCH   256
#define DIM     768
#define NVOCAB  100000
#define VTOP    80
#define SEC     (BATCH*DIM)   // 196608 floats per output section

// ---------------- device scratch (static globals; no allocation) ----------------
__device__ float g_inv_norm[NVOCAB];
__device__ float g_x[BATCH*3072];
__device__ float g_h1[BATCH*2304];
__device__ float g_h2[BATCH*1700];
__device__ float g_h3[BATCH*1000];
__device__ float g_raw4[BATCH*DIM];
__device__ float g_model[BATCH*DIM];
__device__ float g_sims[BATCH*NVOCAB];          // ~102 MB
__device__ int   g_topk[BATCH*VTOP];
__device__ float g_word[BATCH*VTOP*DIM];        // ~63 MB
__device__ float g_board[BATCH*26*DIM];         // ~20 MB

__device__ __forceinline__ float warp_sum(float v) {
#pragma unroll
    for (int o = 16; o; o >>= 1) v += __shfl_xor_sync(0xffffffffu, v, o);
    return v;
}

// ---------------- vocab inverse norms ----------------
__global__ __launch_bounds__(256) void vocab_norms(const float* __restrict__ vocab, int NV) {
    int row = blockIdx.x * 8 + (threadIdx.x >> 5);
    int lane = threadIdx.x & 31;
    if (row >= NV) return;
    const float* src = vocab + (size_t)row * DIM;
    float s = 0.f;
#pragma unroll 4
    for (int d = lane; d < DIM; d += 32) { float v = src[d]; s += v * v; }
    s = warp_sum(s);
    if (lane == 0) g_inv_norm[row] = 1.0f / fmaxf(sqrtf(s), 1e-12f);
}

// ---------------- board prep: normalized words + pooled MLP input ----------------
__global__ __launch_bounds__(256) void board_prep(
    const float* __restrict__ pos, const float* __restrict__ neg,
    const float* __restrict__ neut, const float* __restrict__ assas)
{
    int b = blockIdx.x;
    int t = threadIdx.x;
    int warp = t >> 5, lane = t & 31;

    // --- per-word L2-normalized embeddings into g_board, order: pos(0-8) neg(9-17) neut(18-24) assas(25)
    for (int w = warp; w < 26; w += 8) {
        const float* src;
        if (w < 9)       src = pos  + ((size_t)b * 9 + w) * DIM;
        else if (w < 18) src = neg  + ((size_t)b * 9 + (w - 9)) * DIM;
        else if (w < 25) src = neut + ((size_t)b * 7 + (w - 18)) * DIM;
        else             src = assas + (size_t)b * DIM;
        float s = 0.f;
        for (int d = lane; d < DIM; d += 32) { float v = src[d]; s += v * v; }
        s = warp_sum(s);
        float inv = 1.0f / fmaxf(sqrtf(s), 1e-8f);
        float* dst = g_board + ((size_t)b * 26 + w) * DIM;
        for (int d = lane; d < DIM; d += 32) dst[d] = src[d] * inv;
    }

    // --- pooled groups -> g_x[b, 3072]: [neg_pool | assassin_raw | neut_pool | pos_pool]
    __shared__ float red[256];
    float* xb = g_x + (size_t)b * 3072;

    // assassin raw copy
#pragma unroll
    for (int r = 0; r < 3; r++) {
        int d = t + 256 * r;
        xb[768 + d] = assas[(size_t)b * DIM + d];
    }

    const float* srcs[3] = { neg, neut, pos };
    const int nw[3] = { 9, 7, 9 };
    const int xoff[3] = { 0, 1536, 2304 };
    for (int g = 0; g < 3; g++) {
        float m[3];
#pragma unroll
        for (int r = 0; r < 3; r++) {
            int d = t + 256 * r;
            float s = 0.f;
            for (int w = 0; w < nw[g]; w++)
                s += srcs[g][((size_t)b * nw[g] + w) * DIM + d];
            m[r] = s / (float)nw[g];
        }
        red[t] = m[0]*m[0] + m[1]*m[1] + m[2]*m[2];
        __syncthreads();
        for (int s = 128; s > 0; s >>= 1) { if (t < s) red[t] += red[t + s]; __syncthreads(); }
        float inv = 1.0f / fmaxf(sqrtf(red[0]), 1e-12f);
        __syncthreads();
#pragma unroll
        for (int r = 0; r < 3; r++) xb[xoff[g] + t + 256 * r] = m[r] * inv;
    }
}

// ---------------- generic 128x128x8 SGEMM ----------------
// BT=false: C[M,N] = A[M,K] @ B[K,N]   (B row-major [K,N])
// BT=true:  C[M,N] = A[M,K] @ B^T      (B row-major [N,K])
// mode 0: +bias(aux[n]); mode 1: +bias, relu; mode 2: *aux[n] (scale)
template<bool BT>
__global__ __launch_bounds__(256) void sgemm128(
    const float* __restrict__ A, const float* __restrict__ B,
    const float* __restrict__ aux, float* __restrict__ C,
    int M, int N, int K, int mode)
{
    __shared__ float As[8][128];
    __shared__ float Bs[8][128];
    int tid = threadIdx.x;
    int m0 = blockIdx.y * 128, n0 = blockIdx.x * 128;
    int tx = tid & 15, ty = tid >> 4;

    float acc[8][8];
#pragma unroll
    for (int i = 0; i < 8; i++)
#pragma unroll
        for (int j = 0; j < 8; j++) acc[i][j] = 0.f;

    int lr = tid >> 1;            // 0..127
    int lc = (tid & 1) * 4;       // 0 or 4
    int bnr = tid >> 5;           // 0..7 (k row) for NN B
    int bnc = (tid & 31) * 4;     // n offset for NN B

    for (int k0 = 0; k0 < K; k0 += 8) {
        float4 av = make_float4(0.f, 0.f, 0.f, 0.f);
        {
            int gm = m0 + lr, gk = k0 + lc;
            if (gm < M && gk < K) av = *(const float4*)(A + (size_t)gm * K + gk);
        }
        As[lc + 0][lr] = av.x; As[lc + 1][lr] = av.y;
        As[lc + 2][lr] = av.z; As[lc + 3][lr] = av.w;

        if (BT) {
            float4 bv = make_float4(0.f, 0.f, 0.f, 0.f);
            int gn = n0 + lr, gk = k0 + lc;
            if (gn < N && gk < K) bv = *(const float4*)(B + (size_t)gn * K + gk);
            Bs[lc + 0][lr] = bv.x; Bs[lc + 1][lr] = bv.y;
            Bs[lc + 2][lr] = bv.z; Bs[lc + 3][lr] = bv.w;
        } else {
            float4 bv = make_float4(0.f, 0.f, 0.f, 0.f);
            int gk = k0 + bnr, gn = n0 + bnc;
            if (gk < K && gn < N) bv = *(const float4*)(B + (size_t)gk * N + gn);
            *(float4*)&Bs[bnr][bnc] = bv;
        }
        __syncthreads();

#pragma unroll
        for (int kk = 0; kk < 8; kk++) {
            float4 a0 = *(const float4*)&As[kk][ty * 8];
            float4 a1 = *(const float4*)&As[kk][ty * 8 + 4];
            float4 b0 = *(const float4*)&Bs[kk][tx * 8];
            float4 b1 = *(const float4*)&Bs[kk][tx * 8 + 4];
            float ar[8] = { a0.x, a0.y, a0.z, a0.w, a1.x, a1.y, a1.z, a1.w };
            float br[8] = { b0.x, b0.y, b0.z, b0.w, b1.x, b1.y, b1.z, b1.w };
#pragma unroll
            for (int i = 0; i < 8; i++)
#pragma unroll
                for (int j = 0; j < 8; j++)
                    acc[i][j] += ar[i] * br[j];
        }
        __syncthreads();
    }

#pragma unroll
    for (int i = 0; i < 8; i++) {
        int gm = m0 + ty * 8 + i;
        if (gm >= M) continue;
#pragma unroll
        for (int j = 0; j < 8; j++) {
            int gn = n0 + tx * 8 + j;
            if (gn >= N) continue;
            float v = acc[i][j];
            if (mode == 2) v *= aux[gn];
            else { v += aux[gn]; if (mode == 1) v = fmaxf(v, 0.f); }
            C[(size_t)gm * N + gn] = v;
        }
    }
}

// ---------------- row L2 normalize of raw layer-4 output -> g_model and out[sec0] ----------------
__global__ __launch_bounds__(256) void norm_rows(float* __restrict__ out) {
    int b = blockIdx.x, t = threadIdx.x;
    __shared__ float red[256];
    const float* in = g_raw4 + (size_t)b * DIM;
    float v0 = in[t], v1 = in[t + 256], v2 = in[t + 512];
    red[t] = v0 * v0 + v1 * v1 + v2 * v2;
    __syncthreads();
    for (int s = 128; s > 0; s >>= 1) { if (t < s) red[t] += red[t + s]; __syncthreads(); }
    float inv = 1.0f / fmaxf(sqrtf(red[0]), 1e-12f);
    float* gm = g_model + (size_t)b * DIM;
    float* om = out + (size_t)b * DIM;
    gm[t] = v0 * inv;        om[t] = v0 * inv;
    gm[t + 256] = v1 * inv;  om[t + 256] = v1 * inv;
    gm[t + 512] = v2 * inv;  om[t + 512] = v2 * inv;
}

// ---------------- top-80 per row: histogram threshold + exact rank select ----------------
__global__ __launch_bounds__(256) void topk_kernel(int NV) {
    __shared__ unsigned int hist[2048];
    __shared__ float cval[2048];
    __shared__ int   cidx[2048];
    __shared__ int s_cnt, s_thr;
    int b = blockIdx.x, t = threadIdx.x;
    for (int i = t; i < 2048; i += 256) hist[i] = 0;
    if (t == 0) s_cnt = 0;
    __syncthreads();

    const float* row = g_sims + (size_t)b * NV;
    for (int n = t; n < NV; n += 256) {
        float v = row[n];
        int bin = (int)((v + 1.0f) * 1024.0f);
        bin = min(max(bin, 0), 2047);
        atomicAdd(&hist[bin], 1u);
    }
    __syncthreads();
    if (t == 0) {
        unsigned int c = 0; int bin = 2047;
        for (; bin >= 0; bin--) { c += hist[bin]; if (c >= VTOP) break; }
        s_thr = bin;
    }
    __syncthreads();
    int thr = s_thr;
    for (int n = t; n < NV; n += 256) {
        float v = row[n];
        int bin = (int)((v + 1.0f) * 1024.0f);
        bin = min(max(bin, 0), 2047);
        if (bin >= thr) {
            int p = atomicAdd(&s_cnt, 1);
            if (p < 2048) { cval[p] = v; cidx[p] = n; }
        }
    }
    __syncthreads();
    int C = min(s_cnt, 2048);
    // exact rank with lax.top_k tie-break: value desc, index asc
    for (int i = t; i < C; i += 256) {
        float vi = cval[i]; int ii = cidx[i];
        int r = 0;
        for (int j = 0; j < C; j++) {
            float vj = cval[j];
            r += (vj > vi) || (vj == vi && cidx[j] < ii);
        }
        if (r < VTOP) g_topk[b * VTOP + r] = ii;
    }
}

// ---------------- gather normalized word embeddings; write out[sec1] for v==0 ----------------
__global__ __launch_bounds__(256) void gather_kernel(const float* __restrict__ vocab, float* __restrict__ out) {
    int v = blockIdx.x, b = blockIdx.y, t = threadIdx.x;
    int idx = g_topk[b * VTOP + v];
    float inv = g_inv_norm[idx];
    const float* src = vocab + (size_t)idx * DIM;
    float* dst = g_word + ((size_t)b * VTOP + v) * DIM;
    for (int d = t; d < DIM; d += 256) {
        float val = src[d] * inv;
        dst[d] = val;
        if (v == 0) out[SEC + (size_t)b * DIM + d] = val;
    }
}

// ---------------- scoring + reward + selection + pooling ----------------
__global__ __launch_bounds__(256) void score_kernel(float* __restrict__ out) {
    int b = blockIdx.x, t = threadIdx.x;
    int warp = t >> 5, lane = t & 31;
    __shared__ float S[VTOP][26];
    __shared__ float tot[VTOP];
    __shared__ unsigned char inmax[VTOP], inmin[VTOP];
    __shared__ float red[256];

    // Phase A: cosine scores S[v][j] = word_v . board_j (both unit vectors)
    for (int v = warp; v < VTOP; v += 8) {
        if (lane < 26) {
            const float4* w = (const float4*)(g_word + ((size_t)b * VTOP + v) * DIM);
            const float4* brd = (const float4*)(g_board + ((size_t)b * 26 + lane) * DIM);
            float acc = 0.f;
#pragma unroll 8
            for (int d = 0; d < DIM / 4; d++) {
                float4 a = w[d], c = brd[d];
                acc += a.x * c.x + a.y * c.y + a.z * c.z + a.w * c.w;
            }
            S[v][lane] = acc;
        }
    }
    __syncthreads();

    // Phase B: num_correct, secondary reward, tot (exact small floats)
    if (t < VTOP) {
        float maxbad = -1e30f;
#pragma unroll
        for (int j = 9; j < 26; j++) maxbad = fmaxf(maxbad, S[t][j]);
        int nc = 0;
#pragma unroll
        for (int j = 0; j < 9; j++) nc += (S[t][j] >= maxbad) ? 1 : 0;
        int jm = 25;
        for (int j = 9; j < 26; j++) { if (S[t][j] == maxbad) { jm = j; break; } }
        float sec = (jm <= 17) ? 0.0f : ((jm <= 24) ? 1.0f : -10.0f);
        tot[t] = (float)nc + sec;
    }
    __syncthreads();

    // Phase C: top-40 / bottom-40 selection with stable tie-break (lower index first)
    if (t < VTOP) {
        float tv = tot[t];
        int rmax = 0, rmin = 0;
        for (int u = 0; u < VTOP; u++) {
            float tu = tot[u];
            rmax += (tu > tv) || (tu == tv && u < t);
            rmin += (tu < tv) || (tu == tv && u < t);
        }
        inmax[t] = (rmax < VTOP / 2);
        inmin[t] = (rmin < VTOP / 2);
    }
    __syncthreads();

    // Phase D: pool selected embeddings -> mean -> normalize -> out[sec2], out[sec3]
    float smax[3] = {0.f, 0.f, 0.f}, smin[3] = {0.f, 0.f, 0.f};
    for (int v = 0; v < VTOP; v++) {
        const float* w = g_word + ((size_t)b * VTOP + v) * DIM;
        bool fx = inmax[v], fn = inmin[v];
#pragma unroll
        for (int r = 0; r < 3; r++) {
            float val = w[t + 256 * r];
            if (fx) smax[r] += val;
            if (fn) smin[r] += val;
        }
    }
#pragma unroll
    for (int r = 0; r < 3; r++) { smax[r] *= (1.0f / 40.0f); smin[r] *= (1.0f / 40.0f); }

    red[t] = smax[0]*smax[0] + smax[1]*smax[1] + smax[2]*smax[2];
    __syncthreads();
    for (int s = 128; s > 0; s >>= 1) { if (t < s) red[t] += red[t + s]; __syncthreads(); }
    float invx = 1.0f / fmaxf(sqrtf(red[0]), 1e-12f);
    __syncthreads();
#pragma unroll
    for (int r = 0; r < 3; r++) out[2 * SEC + (size_t)b * DIM + t + 256 * r] = smax[r] * invx;

    red[t] = smin[0]*smin[0] + smin[1]*smin[1] + smin[2]*smin[2];
    __syncthreads();
    for (int s = 128; s > 0; s >>= 1) { if (t < s) red[t] += red[t + s]; __syncthreads(); }
    float invn = 1.0f / fmaxf(sqrtf(red[0]), 1e-12f);
    __syncthreads();
#pragma unroll
    for (int r = 0; r < 3; r++) out[3 * SEC + (size_t)b * DIM + t + 256 * r] = smin[r] * invn;
}

// ---------------- launch ----------------
extern "C" void kernel_launch(void* const* d_in, const int* in_sizes, int n_in,
                              void* d_out, int out_size)
{
    const float* pos   = (const float*)d_in[0];
    const float* neg   = (const float*)d_in[1];
    const float* neut  = (const float*)d_in[2];
    const float* assas = (const float*)d_in[3];
    const float* vocab = (const float*)d_in[4];
    const float* W1 = (const float*)d_in[5];  const float* b1 = (const float*)d_in[6];
    const float* W2 = (const float*)d_in[7];  const float* b2 = (const float*)d_in[8];
    const float* W3 = (const float*)d_in[9];  const float* b3 = (const float*)d_in[10];
    const float* W4 = (const float*)d_in[11]; const float* b4 = (const float*)d_in[12];
    float* out = (float*)d_out;
    int NV = in_sizes[4] / DIM;

    float *p_x, *p_h1, *p_h2, *p_h3, *p_raw4, *p_model, *p_sims, *p_inv;
    cudaGetSymbolAddress((void**)&p_x,     g_x);
    cudaGetSymbolAddress((void**)&p_h1,    g_h1);
    cudaGetSymbolAddress((void**)&p_h2,    g_h2);
    cudaGetSymbolAddress((void**)&p_h3,    g_h3);
    cudaGetSymbolAddress((void**)&p_raw4,  g_raw4);
    cudaGetSymbolAddress((void**)&p_model, g_model);
    cudaGetSymbolAddress((void**)&p_sims,  g_sims);
    cudaGetSymbolAddress((void**)&p_inv,   g_inv_norm);

    vocab_norms<<<(NV + 7) / 8, 256>>>(vocab, NV);
    board_prep<<<BATCH, 256>>>(pos, neg, neut, assas);

    dim3 g1((2304 + 127) / 128, 2);
    sgemm128<false><<<g1, 256>>>(p_x,  W1, b1, p_h1,   BATCH, 2304, 3072, 1);
    dim3 g2((1700 + 127) / 128, 2);
    sgemm128<false><<<g2, 256>>>(p_h1, W2, b2, p_h2,   BATCH, 1700, 2304, 1);
    dim3 g3((1000 + 127) / 128, 2);
    sgemm128<false><<<g3, 256>>>(p_h2, W3, b3, p_h3,   BATCH, 1000, 1700, 1);
    dim3 g4((768 + 127) / 128, 2);
    sgemm128<false><<<g4, 256>>>(p_h3, W4, b4, p_raw4, BATCH, 768, 1000, 0);

    norm_rows<<<BATCH, 256>>>(out);

    dim3 gs((NV + 127) / 128, 2);
    sgemm128<true><<<gs, 256>>>(p_model, vocab, p_inv, p_sims, BATCH, NV, DIM, 2);

    topk_kernel<<<BATCH, 256>>>(NV);
    gather_kernel<<<dim3(VTOP, BATCH), 256>>>(vocab, out);
    score_kernel<<<BATCH, 256>>>(out);
}

// round 7
// speedup vs baseline: 1.0133x; 1.0007x over previous
#include <cuda_runtime.h>
#include <math.h>

#define BATCH   256
#define DIM     768
#define NVOCAB  100000
#define VTOP    80
#define SEC     (BATCH*DIM)   // 196608 floats per output section

// ---------------- device scratch (static globals; no allocation) ----------------
__device__ float g_inv_norm[NVOCAB];
__device__ float g_x[BATCH*3072];
__device__ float g_h1[BATCH*2304];
__device__ float g_h2[BATCH*1700];
__device__ float g_h3[BATCH*1000];
__device__ float g_raw4[BATCH*DIM];
__device__ float g_model[BATCH*DIM];
__device__ float g_sims[BATCH*NVOCAB];          // ~102 MB
__device__ int   g_topk[BATCH*VTOP];
__device__ float g_word[BATCH*VTOP*DIM];        // ~63 MB
__device__ float g_board[BATCH*26*DIM];         // ~20 MB

__device__ __forceinline__ float warp_sum(float v) {
#pragma unroll
    for (int o = 16; o; o >>= 1) v += __shfl_xor_sync(0xffffffffu, v, o);
    return v;
}

// ---------------- vocab inverse norms ----------------
__global__ __launch_bounds__(256) void vocab_norms(const float* __restrict__ vocab, int NV) {
    int row = blockIdx.x * 8 + (threadIdx.x >> 5);
    int lane = threadIdx.x & 31;
    if (row >= NV) return;
    const float* src = vocab + (size_t)row * DIM;
    float s = 0.f;
#pragma unroll 4
    for (int d = lane; d < DIM; d += 32) { float v = src[d]; s += v * v; }
    s = warp_sum(s);
    if (lane == 0) g_inv_norm[row] = 1.0f / fmaxf(sqrtf(s), 1e-12f);
}

// ---------------- board prep: normalized words + pooled MLP input ----------------
__global__ __launch_bounds__(256) void board_prep(
    const float* __restrict__ pos, const float* __restrict__ neg,
    const float* __restrict__ neut, const float* __restrict__ assas)
{
    int b = blockIdx.x;
    int t = threadIdx.x;
    int warp = t >> 5, lane = t & 31;

    // --- per-word L2-normalized embeddings into g_board, order: pos(0-8) neg(9-17) neut(18-24) assas(25)
    for (int w = warp; w < 26; w += 8) {
        const float* src;
        if (w < 9)       src = pos  + ((size_t)b * 9 + w) * DIM;
        else if (w < 18) src = neg  + ((size_t)b * 9 + (w - 9)) * DIM;
        else if (w < 25) src = neut + ((size_t)b * 7 + (w - 18)) * DIM;
        else             src = assas + (size_t)b * DIM;
        float s = 0.f;
        for (int d = lane; d < DIM; d += 32) { float v = src[d]; s += v * v; }
        s = warp_sum(s);
        float inv = 1.0f / fmaxf(sqrtf(s), 1e-8f);
        float* dst = g_board + ((size_t)b * 26 + w) * DIM;
        for (int d = lane; d < DIM; d += 32) dst[d] = src[d] * inv;
    }

    // --- pooled groups -> g_x[b, 3072]: [neg_pool | assassin_raw | neut_pool | pos_pool]
    __shared__ float red[256];
    float* xb = g_x + (size_t)b * 3072;

    // assassin raw copy
#pragma unroll
    for (int r = 0; r < 3; r++) {
        int d = t + 256 * r;
        xb[768 + d] = assas[(size_t)b * DIM + d];
    }

    const float* srcs[3] = { neg, neut, pos };
    const int nw[3] = { 9, 7, 9 };
    const int xoff[3] = { 0, 1536, 2304 };
    for (int g = 0; g < 3; g++) {
        float m[3];
#pragma unroll
        for (int r = 0; r < 3; r++) {
            int d = t + 256 * r;
            float s = 0.f;
            for (int w = 0; w < nw[g]; w++)
                s += srcs[g][((size_t)b * nw[g] + w) * DIM + d];
            m[r] = s / (float)nw[g];
        }
        red[t] = m[0]*m[0] + m[1]*m[1] + m[2]*m[2];
        __syncthreads();
        for (int s = 128; s > 0; s >>= 1) { if (t < s) red[t] += red[t + s]; __syncthreads(); }
        float inv = 1.0f / fmaxf(sqrtf(red[0]), 1e-12f);
        __syncthreads();
#pragma unroll
        for (int r = 0; r < 3; r++) xb[xoff[g] + t + 256 * r] = m[r] * inv;
    }
}

// ---------------- generic 128x128x8 SGEMM ----------------
// BT=false: C[M,N] = A[M,K] @ B[K,N]   (B row-major [K,N])
// BT=true:  C[M,N] = A[M,K] @ B^T      (B row-major [N,K])
// mode 0: +bias(aux[n]); mode 1: +bias, relu; mode 2: *aux[n] (scale)
template<bool BT>
__global__ __launch_bounds__(256) void sgemm128(
    const float* __restrict__ A, const float* __restrict__ B,
    const float* __restrict__ aux, float* __restrict__ C,
    int M, int N, int K, int mode)
{
    __shared__ float As[8][128];
    __shared__ float Bs[8][128];
    int tid = threadIdx.x;
    int m0 = blockIdx.y * 128, n0 = blockIdx.x * 128;
    int tx = tid & 15, ty = tid >> 4;

    float acc[8][8];
#pragma unroll
    for (int i = 0; i < 8; i++)
#pragma unroll
        for (int j = 0; j < 8; j++) acc[i][j] = 0.f;

    int lr = tid >> 1;            // 0..127
    int lc = (tid & 1) * 4;       // 0 or 4
    int bnr = tid >> 5;           // 0..7 (k row) for NN B
    int bnc = (tid & 31) * 4;     // n offset for NN B

    for (int k0 = 0; k0 < K; k0 += 8) {
        float4 av = make_float4(0.f, 0.f, 0.f, 0.f);
        {
            int gm = m0 + lr, gk = k0 + lc;
            if (gm < M && gk < K) av = *(const float4*)(A + (size_t)gm * K + gk);
        }
        As[lc + 0][lr] = av.x; As[lc + 1][lr] = av.y;
        As[lc + 2][lr] = av.z; As[lc + 3][lr] = av.w;

        if (BT) {
            float4 bv = make_float4(0.f, 0.f, 0.f, 0.f);
            int gn = n0 + lr, gk = k0 + lc;
            if (gn < N && gk < K) bv = *(const float4*)(B + (size_t)gn * K + gk);
            Bs[lc + 0][lr] = bv.x; Bs[lc + 1][lr] = bv.y;
            Bs[lc + 2][lr] = bv.z; Bs[lc + 3][lr] = bv.w;
        } else {
            float4 bv = make_float4(0.f, 0.f, 0.f, 0.f);
            int gk = k0 + bnr, gn = n0 + bnc;
            if (gk < K && gn < N) bv = *(const float4*)(B + (size_t)gk * N + gn);
            *(float4*)&Bs[bnr][bnc] = bv;
        }
        __syncthreads();

#pragma unroll
        for (int kk = 0; kk < 8; kk++) {
            float4 a0 = *(const float4*)&As[kk][ty * 8];
            float4 a1 = *(const float4*)&As[kk][ty * 8 + 4];
            float4 b0 = *(const float4*)&Bs[kk][tx * 8];
            float4 b1 = *(const float4*)&Bs[kk][tx * 8 + 4];
            float ar[8] = { a0.x, a0.y, a0.z, a0.w, a1.x, a1.y, a1.z, a1.w };
            float br[8] = { b0.x, b0.y, b0.z, b0.w, b1.x, b1.y, b1.z, b1.w };
#pragma unroll
            for (int i = 0; i < 8; i++)
#pragma unroll
                for (int j = 0; j < 8; j++)
                    acc[i][j] += ar[i] * br[j];
        }
        __syncthreads();
    }

#pragma unroll
    for (int i = 0; i < 8; i++) {
        int gm = m0 + ty * 8 + i;
        if (gm >= M) continue;
#pragma unroll
        for (int j = 0; j < 8; j++) {
            int gn = n0 + tx * 8 + j;
            if (gn >= N) continue;
            float v = acc[i][j];
            if (mode == 2) v *= aux[gn];
            else { v += aux[gn]; if (mode == 1) v = fmaxf(v, 0.f); }
            C[(size_t)gm * N + gn] = v;
        }
    }
}

// ---------------- row L2 normalize of raw layer-4 output -> g_model and out[sec0] ----------------
__global__ __launch_bounds__(256) void norm_rows(float* __restrict__ out) {
    int b = blockIdx.x, t = threadIdx.x;
    __shared__ float red[256];
    const float* in = g_raw4 + (size_t)b * DIM;
    float v0 = in[t], v1 = in[t + 256], v2 = in[t + 512];
    red[t] = v0 * v0 + v1 * v1 + v2 * v2;
    __syncthreads();
    for (int s = 128; s > 0; s >>= 1) { if (t < s) red[t] += red[t + s]; __syncthreads(); }
    float inv = 1.0f / fmaxf(sqrtf(red[0]), 1e-12f);
    float* gm = g_model + (size_t)b * DIM;
    float* om = out + (size_t)b * DIM;
    gm[t] = v0 * inv;        om[t] = v0 * inv;
    gm[t + 256] = v1 * inv;  om[t + 256] = v1 * inv;
    gm[t + 512] = v2 * inv;  om[t + 512] = v2 * inv;
}

// ---------------- top-80 per row: histogram threshold + exact rank select ----------------
__global__ __launch_bounds__(256) void topk_kernel(int NV) {
    __shared__ unsigned int hist[2048];
    __shared__ float cval[2048];
    __shared__ int   cidx[2048];
    __shared__ int s_cnt, s_thr;
    int b = blockIdx.x, t = threadIdx.x;
    for (int i = t; i < 2048; i += 256) hist[i] = 0;
    if (t == 0) s_cnt = 0;
    __syncthreads();

    const float* row = g_sims + (size_t)b * NV;
    for (int n = t; n < NV; n += 256) {
        float v = row[n];
        int bin = (int)((v + 1.0f) * 1024.0f);
        bin = min(max(bin, 0), 2047);
        atomicAdd(&hist[bin], 1u);
    }
    __syncthreads();
    if (t == 0) {
        unsigned int c = 0; int bin = 2047;
        for (; bin >= 0; bin--) { c += hist[bin]; if (c >= VTOP) break; }
        s_thr = bin;
    }
    __syncthreads();
    int thr = s_thr;
    for (int n = t; n < NV; n += 256) {
        float v = row[n];
        int bin = (int)((v + 1.0f) * 1024.0f);
        bin = min(max(bin, 0), 2047);
        if (bin >= thr) {
            int p = atomicAdd(&s_cnt, 1);
            if (p < 2048) { cval[p] = v; cidx[p] = n; }
        }
    }
    __syncthreads();
    int C = min(s_cnt, 2048);
    // exact rank with lax.top_k tie-break: value desc, index asc
    for (int i = t; i < C; i += 256) {
        float vi = cval[i]; int ii = cidx[i];
        int r = 0;
        for (int j = 0; j < C; j++) {
            float vj = cval[j];
            r += (vj > vi) || (vj == vi && cidx[j] < ii);
        }
        if (r < VTOP) g_topk[b * VTOP + r] = ii;
    }
}

// ---------------- gather normalized word embeddings; write out[sec1] for v==0 ----------------
__global__ __launch_bounds__(256) void gather_kernel(const float* __restrict__ vocab, float* __restrict__ out) {
    int v = blockIdx.x, b = blockIdx.y, t = threadIdx.x;
    int idx = g_topk[b * VTOP + v];
    float inv = g_inv_norm[idx];
    const float* src = vocab + (size_t)idx * DIM;
    float* dst = g_word + ((size_t)b * VTOP + v) * DIM;
    for (int d = t; d < DIM; d += 256) {
        float val = src[d] * inv;
        dst[d] = val;
        if (v == 0) out[SEC + (size_t)b * DIM + d] = val;
    }
}

// ---------------- scoring + reward + selection + pooling ----------------
__global__ __launch_bounds__(256) void score_kernel(float* __restrict__ out) {
    int b = blockIdx.x, t = threadIdx.x;
    int warp = t >> 5, lane = t & 31;
    __shared__ float S[VTOP][26];
    __shared__ float tot[VTOP];
    __shared__ unsigned char inmax[VTOP], inmin[VTOP];
    __shared__ float red[256];

    // Phase A: cosine scores S[v][j] = word_v . board_j (both unit vectors)
    for (int v = warp; v < VTOP; v += 8) {
        if (lane < 26) {
            const float4* w = (const float4*)(g_word + ((size_t)b * VTOP + v) * DIM);
            const float4* brd = (const float4*)(g_board + ((size_t)b * 26 + lane) * DIM);
            float acc = 0.f;
#pragma unroll 8
            for (int d = 0; d < DIM / 4; d++) {
                float4 a = w[d], c = brd[d];
                acc += a.x * c.x + a.y * c.y + a.z * c.z + a.w * c.w;
            }
            S[v][lane] = acc;
        }
    }
    __syncthreads();

    // Phase B: num_correct, secondary reward, tot (exact small floats)
    if (t < VTOP) {
        float maxbad = -1e30f;
#pragma unroll
        for (int j = 9; j < 26; j++) maxbad = fmaxf(maxbad, S[t][j]);
        int nc = 0;
#pragma unroll
        for (int j = 0; j < 9; j++) nc += (S[t][j] >= maxbad) ? 1 : 0;
        int jm = 25;
        for (int j = 9; j < 26; j++) { if (S[t][j] == maxbad) { jm = j; break; } }
        float sec = (jm <= 17) ? 0.0f : ((jm <= 24) ? 1.0f : -10.0f);
        tot[t] = (float)nc + sec;
    }
    __syncthreads();

    // Phase C: top-40 / bottom-40 selection with stable tie-break (lower index first)
    if (t < VTOP) {
        float tv = tot[t];
        int rmax = 0, rmin = 0;
        for (int u = 0; u < VTOP; u++) {
            float tu = tot[u];
            rmax += (tu > tv) || (tu == tv && u < t);
            rmin += (tu < tv) || (tu == tv && u < t);
        }
        inmax[t] = (rmax < VTOP / 2);
        inmin[t] = (rmin < VTOP / 2);
    }
    __syncthreads();

    // Phase D: pool selected embeddings -> mean -> normalize -> out[sec2], out[sec3]
    float smax[3] = {0.f, 0.f, 0.f}, smin[3] = {0.f, 0.f, 0.f};
    for (int v = 0; v < VTOP; v++) {
        const float* w = g_word + ((size_t)b * VTOP + v) * DIM;
        bool fx = inmax[v], fn = inmin[v];
#pragma unroll
        for (int r = 0; r < 3; r++) {
            float val = w[t + 256 * r];
            if (fx) smax[r] += val;
            if (fn) smin[r] += val;
        }
    }
#pragma unroll
    for (int r = 0; r < 3; r++) { smax[r] *= (1.0f / 40.0f); smin[r] *= (1.0f / 40.0f); }

    red[t] = smax[0]*smax[0] + smax[1]*smax[1] + smax[2]*smax[2];
    __syncthreads();
    for (int s = 128; s > 0; s >>= 1) { if (t < s) red[t] += red[t + s]; __syncthreads(); }
    float invx = 1.0f / fmaxf(sqrtf(red[0]), 1e-12f);
    __syncthreads();
#pragma unroll
    for (int r = 0; r < 3; r++) out[2 * SEC + (size_t)b * DIM + t + 256 * r] = smax[r] * invx;

    red[t] = smin[0]*smin[0] + smin[1]*smin[1] + smin[2]*smin[2];
    __syncthreads();
    for (int s = 128; s > 0; s >>= 1) { if (t < s) red[t] += red[t + s]; __syncthreads(); }
    float invn = 1.0f / fmaxf(sqrtf(red[0]), 1e-12f);
    __syncthreads();
#pragma unroll
    for (int r = 0; r < 3; r++) out[3 * SEC + (size_t)b * DIM + t + 256 * r] = smin[r] * invn;
}

// ---------------- launch ----------------
extern "C" void kernel_launch(void* const* d_in, const int* in_sizes, int n_in,
                              void* d_out, int out_size)
{
    const float* pos   = (const float*)d_in[0];
    const float* neg   = (const float*)d_in[1];
    const float* neut  = (const float*)d_in[2];
    const float* assas = (const float*)d_in[3];
    const float* vocab = (const float*)d_in[4];
    const float* W1 = (const float*)d_in[5];  const float* b1 = (const float*)d_in[6];
    const float* W2 = (const float*)d_in[7];  const float* b2 = (const float*)d_in[8];
    const float* W3 = (const float*)d_in[9];  const float* b3 = (const float*)d_in[10];
    const float* W4 = (const float*)d_in[11]; const float* b4 = (const float*)d_in[12];
    float* out = (float*)d_out;
    int NV = in_sizes[4] / DIM;

    float *p_x, *p_h1, *p_h2, *p_h3, *p_raw4, *p_model, *p_sims, *p_inv;
    cudaGetSymbolAddress((void**)&p_x,     g_x);
    cudaGetSymbolAddress((void**)&p_h1,    g_h1);
    cudaGetSymbolAddress((void**)&p_h2,    g_h2);
    cudaGetSymbolAddress((void**)&p_h3,    g_h3);
    cudaGetSymbolAddress((void**)&p_raw4,  g_raw4);
    cudaGetSymbolAddress((void**)&p_model, g_model);
    cudaGetSymbolAddress((void**)&p_sims,  g_sims);
    cudaGetSymbolAddress((void**)&p_inv,   g_inv_norm);

    vocab_norms<<<(NV + 7) / 8, 256>>>(vocab, NV);
    board_prep<<<BATCH, 256>>>(pos, neg, neut, assas);

    dim3 g1((2304 + 127) / 128, 2);
    sgemm128<false><<<g1, 256>>>(p_x,  W1, b1, p_h1,   BATCH, 2304, 3072, 1);
    dim3 g2((1700 + 127) / 128, 2);
    sgemm128<false><<<g2, 256>>>(p_h1, W2, b2, p_h2,   BATCH, 1700, 2304, 1);
    dim3 g3((1000 + 127) / 128, 2);
    sgemm128<false><<<g3, 256>>>(p_h2, W3, b3, p_h3,   BATCH, 1000, 1700, 1);
    dim3 g4((768 + 127) / 128, 2);
    sgemm128<false><<<g4, 256>>>(p_h3, W4, b4, p_raw4, BATCH, 768, 1000, 0);

    norm_rows<<<BATCH, 256>>>(out);

    dim3 gs((NV + 127) / 128, 2);
    sgemm128<true><<<gs, 256>>>(p_model, vocab, p_inv, p_sims, BATCH, NV, DIM, 2);

    topk_kernel<<<BATCH, 256>>>(NV);
    gather_kernel<<<dim3(VTOP, BATCH), 256>>>(vocab, out);
    score_kernel<<<BATCH, 256>>>(out);
}

// round 8
// speedup vs baseline: 1.7516x; 1.7286x over previous
#include <cuda_runtime.h>
#include <math.h>

#define BATCH   256
#define DIM     768
#define NVOCAB  100000
#define VTOP    80
#define SEC     (BATCH*DIM)   // 196608 floats per output section

// ---------------- device scratch (static globals; no allocation) ----------------
__device__ float g_inv_norm[NVOCAB];
__device__ float g_x[BATCH*3072];
__device__ float g_h1[BATCH*2304];
__device__ float g_h2[BATCH*1700];
__device__ float g_h3[BATCH*1000];
__device__ float g_raw4[BATCH*DIM];
__device__ float g_model[BATCH*DIM];
__device__ float g_sims[BATCH*NVOCAB];          // ~102 MB
__device__ int   g_topk[BATCH*VTOP];
__device__ float g_word[BATCH*VTOP*DIM];        // ~63 MB
__device__ float g_board[BATCH*26*DIM];         // ~20 MB

__device__ __forceinline__ float warp_sum(float v) {
#pragma unroll
    for (int o = 16; o; o >>= 1) v += __shfl_xor_sync(0xffffffffu, v, o);
    return v;
}

// ---- packed fp32 helpers (sm_100+ f32x2) ----
__device__ __forceinline__ unsigned long long pack2(float x, float y) {
    unsigned long long r;
    asm("mov.b64 %0, {%1, %2};" : "=l"(r) : "f"(x), "f"(y));
    return r;
}
__device__ __forceinline__ float2 unpack2(unsigned long long v) {
    float2 r;
    asm("mov.b64 {%0, %1}, %2;" : "=f"(r.x), "=f"(r.y) : "l"(v));
    return r;
}
__device__ __forceinline__ void fma2(unsigned long long& d, unsigned long long a, unsigned long long b) {
    asm("fma.rn.f32x2 %0, %1, %2, %3;" : "=l"(d) : "l"(a), "l"(b), "l"(d));
}

// ---------------- vocab inverse norms ----------------
__global__ __launch_bounds__(256) void vocab_norms(const float* __restrict__ vocab, int NV) {
    int row = blockIdx.x * 8 + (threadIdx.x >> 5);
    int lane = threadIdx.x & 31;
    if (row >= NV) return;
    const float* src = vocab + (size_t)row * DIM;
    float s = 0.f;
#pragma unroll 4
    for (int d = lane; d < DIM; d += 32) { float v = src[d]; s += v * v; }
    s = warp_sum(s);
    if (lane == 0) g_inv_norm[row] = 1.0f / fmaxf(sqrtf(s), 1e-12f);
}

// ---------------- board prep: normalized words + pooled MLP input ----------------
__global__ __launch_bounds__(256) void board_prep(
    const float* __restrict__ pos, const float* __restrict__ neg,
    const float* __restrict__ neut, const float* __restrict__ assas)
{
    int b = blockIdx.x;
    int t = threadIdx.x;
    int warp = t >> 5, lane = t & 31;

    for (int w = warp; w < 26; w += 8) {
        const float* src;
        if (w < 9)       src = pos  + ((size_t)b * 9 + w) * DIM;
        else if (w < 18) src = neg  + ((size_t)b * 9 + (w - 9)) * DIM;
        else if (w < 25) src = neut + ((size_t)b * 7 + (w - 18)) * DIM;
        else             src = assas + (size_t)b * DIM;
        float s = 0.f;
        for (int d = lane; d < DIM; d += 32) { float v = src[d]; s += v * v; }
        s = warp_sum(s);
        float inv = 1.0f / fmaxf(sqrtf(s), 1e-8f);
        float* dst = g_board + ((size_t)b * 26 + w) * DIM;
        for (int d = lane; d < DIM; d += 32) dst[d] = src[d] * inv;
    }

    __shared__ float red[256];
    float* xb = g_x + (size_t)b * 3072;

#pragma unroll
    for (int r = 0; r < 3; r++) {
        int d = t + 256 * r;
        xb[768 + d] = assas[(size_t)b * DIM + d];
    }

    const float* srcs[3] = { neg, neut, pos };
    const int nw[3] = { 9, 7, 9 };
    const int xoff[3] = { 0, 1536, 2304 };
    for (int g = 0; g < 3; g++) {
        float m[3];
#pragma unroll
        for (int r = 0; r < 3; r++) {
            int d = t + 256 * r;
            float s = 0.f;
            for (int w = 0; w < nw[g]; w++)
                s += srcs[g][((size_t)b * nw[g] + w) * DIM + d];
            m[r] = s / (float)nw[g];
        }
        red[t] = m[0]*m[0] + m[1]*m[1] + m[2]*m[2];
        __syncthreads();
        for (int s = 128; s > 0; s >>= 1) { if (t < s) red[t] += red[t + s]; __syncthreads(); }
        float inv = 1.0f / fmaxf(sqrtf(red[0]), 1e-12f);
        __syncthreads();
#pragma unroll
        for (int r = 0; r < 3; r++) xb[xoff[g] + t + 256 * r] = m[r] * inv;
    }
}

// ---------------- double-buffered f32x2 SGEMM ----------------
// BT=false: C[M,N] = A[M,K] @ B[K,N]   (B row-major [K,N])
// BT=true:  C[M,N] = A[M,K] @ B^T      (B row-major [N,K])
// mode 0: +bias(aux[n]); mode 1: +bias, relu; mode 2: *aux[n] (scale)
// Requires (BM/TM)*(BN/TN)==256, BM*BK%1024==0, BN*BK%1024==0, TM%4==0, TN%4==0.
template<int BM, int BN, int BK, int TM, int TN, bool BT>
__global__ __launch_bounds__(256) void gemm_f32x2(
    const float* __restrict__ A, const float* __restrict__ B,
    const float* __restrict__ aux, float* __restrict__ C,
    int M, int N, int K, int mode)
{
    __shared__ float As[2][BK][BM];
    __shared__ float Bs[2][BK][BN];

    const int tid = threadIdx.x;
    const int m0 = blockIdx.y * BM, n0 = blockIdx.x * BN;
    const int NX = BN / TN;
    const int tx = tid % NX, ty = tid / NX;

    const int ACH = (BM * BK) / 1024;   // float4 chunks per thread for A
    const int BCH = (BN * BK) / 1024;   // same count for B

    unsigned long long acc[TM][TN / 2];
#pragma unroll
    for (int i = 0; i < TM; i++)
#pragma unroll
        for (int j = 0; j < TN / 2; j++) acc[i][j] = 0ull;

    float4 ra[ACH], rb[BCH];
    const float4 z4 = make_float4(0.f, 0.f, 0.f, 0.f);

    // ---- load helpers (manually inlined via lambdas) ----
    auto load_tile = [&](int k0) {
#pragma unroll
        for (int c = 0; c < ACH; c++) {
            int li = tid + c * 256;
            int row = li / (BK / 4);
            int kc  = (li % (BK / 4)) * 4;
            int gm = m0 + row, gk = k0 + kc;
            ra[c] = (gm < M && gk < K) ? *(const float4*)(A + (size_t)gm * K + gk) : z4;
        }
        if (BT) {
#pragma unroll
            for (int c = 0; c < BCH; c++) {
                int li = tid + c * 256;
                int row = li / (BK / 4);
                int kc  = (li % (BK / 4)) * 4;
                int gn = n0 + row, gk = k0 + kc;
                rb[c] = (gn < N && gk < K) ? *(const float4*)(B + (size_t)gn * K + gk) : z4;
            }
        } else {
#pragma unroll
            for (int c = 0; c < BCH; c++) {
                int li = tid + c * 256;
                int krow = li / (BN / 4);
                int nc   = (li % (BN / 4)) * 4;
                int gk = k0 + krow, gn = n0 + nc;
                rb[c] = (gk < K && gn < N) ? *(const float4*)(B + (size_t)gk * N + gn) : z4;
            }
        }
    };
    auto store_tile = [&](int buf) {
#pragma unroll
        for (int c = 0; c < ACH; c++) {
            int li = tid + c * 256;
            int row = li / (BK / 4);
            int kc  = (li % (BK / 4)) * 4;
            As[buf][kc + 0][row] = ra[c].x;
            As[buf][kc + 1][row] = ra[c].y;
            As[buf][kc + 2][row] = ra[c].z;
            As[buf][kc + 3][row] = ra[c].w;
        }
        if (BT) {
#pragma unroll
            for (int c = 0; c < BCH; c++) {
                int li = tid + c * 256;
                int row = li / (BK / 4);
                int kc  = (li % (BK / 4)) * 4;
                Bs[buf][kc + 0][row] = rb[c].x;
                Bs[buf][kc + 1][row] = rb[c].y;
                Bs[buf][kc + 2][row] = rb[c].z;
                Bs[buf][kc + 3][row] = rb[c].w;
            }
        } else {
#pragma unroll
            for (int c = 0; c < BCH; c++) {
                int li = tid + c * 256;
                int krow = li / (BN / 4);
                int nc   = (li % (BN / 4)) * 4;
                *(float4*)&Bs[buf][krow][nc] = rb[c];
            }
        }
    };

    // prologue
    load_tile(0);
    store_tile(0);
    __syncthreads();

    int cur = 0;
    for (int k0 = 0; k0 < K; k0 += BK) {
        bool more = (k0 + BK) < K;
        if (more) load_tile(k0 + BK);   // LDGs in flight during compute

#pragma unroll
        for (int kk = 0; kk < BK; kk++) {
            float av[TM];
#pragma unroll
            for (int i = 0; i < TM; i += 4)
                *(float4*)&av[i] = *(const float4*)&As[cur][kk][ty * TM + i];
            unsigned long long aa[TM];
#pragma unroll
            for (int i = 0; i < TM; i++) aa[i] = pack2(av[i], av[i]);

            unsigned long long bb[TN / 2];
#pragma unroll
            for (int j = 0; j < TN; j += 4) {
                ulonglong2 tb = *(const ulonglong2*)&Bs[cur][kk][tx * TN + j];
                bb[j / 2]     = tb.x;
                bb[j / 2 + 1] = tb.y;
            }
#pragma unroll
            for (int i = 0; i < TM; i++)
#pragma unroll
                for (int j = 0; j < TN / 2; j++)
                    fma2(acc[i][j], aa[i], bb[j]);
        }

        if (more) {
            store_tile(cur ^ 1);   // safe: other buffer; prior barrier ordered its readers
            __syncthreads();
            cur ^= 1;
        }
    }

    // epilogue
#pragma unroll
    for (int i = 0; i < TM; i++) {
        int gm = m0 + ty * TM + i;
        if (gm >= M) continue;
#pragma unroll
        for (int j = 0; j < TN / 2; j++) {
            float2 v = unpack2(acc[i][j]);
            int gn = n0 + tx * TN + 2 * j;
            if (gn < N) {
                float o = v.x;
                if (mode == 2) o *= aux[gn];
                else { o += aux[gn]; if (mode == 1) o = fmaxf(o, 0.f); }
                C[(size_t)gm * N + gn] = o;
            }
            if (gn + 1 < N) {
                float o = v.y;
                if (mode == 2) o *= aux[gn + 1];
                else { o += aux[gn + 1]; if (mode == 1) o = fmaxf(o, 0.f); }
                C[(size_t)gm * N + gn + 1] = o;
            }
        }
    }
}

// ---------------- row L2 normalize of raw layer-4 output -> g_model and out[sec0] ----------------
__global__ __launch_bounds__(256) void norm_rows(float* __restrict__ out) {
    int b = blockIdx.x, t = threadIdx.x;
    __shared__ float red[256];
    const float* in = g_raw4 + (size_t)b * DIM;
    float v0 = in[t], v1 = in[t + 256], v2 = in[t + 512];
    red[t] = v0 * v0 + v1 * v1 + v2 * v2;
    __syncthreads();
    for (int s = 128; s > 0; s >>= 1) { if (t < s) red[t] += red[t + s]; __syncthreads(); }
    float inv = 1.0f / fmaxf(sqrtf(red[0]), 1e-12f);
    float* gm = g_model + (size_t)b * DIM;
    float* om = out + (size_t)b * DIM;
    gm[t] = v0 * inv;        om[t] = v0 * inv;
    gm[t + 256] = v1 * inv;  om[t + 256] = v1 * inv;
    gm[t + 512] = v2 * inv;  om[t + 512] = v2 * inv;
}

// ---------------- top-80 per row: histogram threshold + exact rank select ----------------
__global__ __launch_bounds__(256) void topk_kernel(int NV) {
    __shared__ unsigned int hist[2048];
    __shared__ float cval[2048];
    __shared__ int   cidx[2048];
    __shared__ int s_cnt, s_thr;
    int b = blockIdx.x, t = threadIdx.x;
    for (int i = t; i < 2048; i += 256) hist[i] = 0;
    if (t == 0) s_cnt = 0;
    __syncthreads();

    const float* row = g_sims + (size_t)b * NV;
    for (int n = t; n < NV; n += 256) {
        float v = row[n];
        int bin = (int)((v + 1.0f) * 1024.0f);
        bin = min(max(bin, 0), 2047);
        atomicAdd(&hist[bin], 1u);
    }
    __syncthreads();
    if (t == 0) {
        unsigned int c = 0; int bin = 2047;
        for (; bin >= 0; bin--) { c += hist[bin]; if (c >= VTOP) break; }
        s_thr = bin;
    }
    __syncthreads();
    int thr = s_thr;
    for (int n = t; n < NV; n += 256) {
        float v = row[n];
        int bin = (int)((v + 1.0f) * 1024.0f);
        bin = min(max(bin, 0), 2047);
        if (bin >= thr) {
            int p = atomicAdd(&s_cnt, 1);
            if (p < 2048) { cval[p] = v; cidx[p] = n; }
        }
    }
    __syncthreads();
    int C = min(s_cnt, 2048);
    for (int i = t; i < C; i += 256) {
        float vi = cval[i]; int ii = cidx[i];
        int r = 0;
        for (int j = 0; j < C; j++) {
            float vj = cval[j];
            r += (vj > vi) || (vj == vi && cidx[j] < ii);
        }
        if (r < VTOP) g_topk[b * VTOP + r] = ii;
    }
}

// ---------------- gather normalized word embeddings; write out[sec1] for v==0 ----------------
__global__ __launch_bounds__(256) void gather_kernel(const float* __restrict__ vocab, float* __restrict__ out) {
    int v = blockIdx.x, b = blockIdx.y, t = threadIdx.x;
    int idx = g_topk[b * VTOP + v];
    float inv = g_inv_norm[idx];
    const float* src = vocab + (size_t)idx * DIM;
    float* dst = g_word + ((size_t)b * VTOP + v) * DIM;
    for (int d = t; d < DIM; d += 256) {
        float val = src[d] * inv;
        dst[d] = val;
        if (v == 0) out[SEC + (size_t)b * DIM + d] = val;
    }
}

// ---------------- scoring + reward + selection + pooling ----------------
__global__ __launch_bounds__(256) void score_kernel(float* __restrict__ out) {
    int b = blockIdx.x, t = threadIdx.x;
    int warp = t >> 5, lane = t & 31;
    __shared__ float S[VTOP][26];
    __shared__ float tot[VTOP];
    __shared__ unsigned char inmax[VTOP], inmin[VTOP];
    __shared__ float red[256];

    for (int v = warp; v < VTOP; v += 8) {
        if (lane < 26) {
            const float4* w = (const float4*)(g_word + ((size_t)b * VTOP + v) * DIM);
            const float4* brd = (const float4*)(g_board + ((size_t)b * 26 + lane) * DIM);
            float acc = 0.f;
#pragma unroll 8
            for (int d = 0; d < DIM / 4; d++) {
                float4 a = w[d], c = brd[d];
                acc += a.x * c.x + a.y * c.y + a.z * c.z + a.w * c.w;
            }
            S[v][lane] = acc;
        }
    }
    __syncthreads();

    if (t < VTOP) {
        float maxbad = -1e30f;
#pragma unroll
        for (int j = 9; j < 26; j++) maxbad = fmaxf(maxbad, S[t][j]);
        int nc = 0;
#pragma unroll
        for (int j = 0; j < 9; j++) nc += (S[t][j] >= maxbad) ? 1 : 0;
        int jm = 25;
        for (int j = 9; j < 26; j++) { if (S[t][j] == maxbad) { jm = j; break; } }
        float sec = (jm <= 17) ? 0.0f : ((jm <= 24) ? 1.0f : -10.0f);
        tot[t] = (float)nc + sec;
    }
    __syncthreads();

    if (t < VTOP) {
        float tv = tot[t];
        int rmax = 0, rmin = 0;
        for (int u = 0; u < VTOP; u++) {
            float tu = tot[u];
            rmax += (tu > tv) || (tu == tv && u < t);
            rmin += (tu < tv) || (tu == tv && u < t);
        }
        inmax[t] = (rmax < VTOP / 2);
        inmin[t] = (rmin < VTOP / 2);
    }
    __syncthreads();

    float smax[3] = {0.f, 0.f, 0.f}, smin[3] = {0.f, 0.f, 0.f};
    for (int v = 0; v < VTOP; v++) {
        const float* w = g_word + ((size_t)b * VTOP + v) * DIM;
        bool fx = inmax[v], fn = inmin[v];
#pragma unroll
        for (int r = 0; r < 3; r++) {
            float val = w[t + 256 * r];
            if (fx) smax[r] += val;
            if (fn) smin[r] += val;
        }
    }
#pragma unroll
    for (int r = 0; r < 3; r++) { smax[r] *= (1.0f / 40.0f); smin[r] *= (1.0f / 40.0f); }

    red[t] = smax[0]*smax[0] + smax[1]*smax[1] + smax[2]*smax[2];
    __syncthreads();
    for (int s = 128; s > 0; s >>= 1) { if (t < s) red[t] += red[t + s]; __syncthreads(); }
    float invx = 1.0f / fmaxf(sqrtf(red[0]), 1e-12f);
    __syncthreads();
#pragma unroll
    for (int r = 0; r < 3; r++) out[2 * SEC + (size_t)b * DIM + t + 256 * r] = smax[r] * invx;

    red[t] = smin[0]*smin[0] + smin[1]*smin[1] + smin[2]*smin[2];
    __syncthreads();
    for (int s = 128; s > 0; s >>= 1) { if (t < s) red[t] += red[t + s]; __syncthreads(); }
    float invn = 1.0f / fmaxf(sqrtf(red[0]), 1e-12f);
    __syncthreads();
#pragma unroll
    for (int r = 0; r < 3; r++) out[3 * SEC + (size_t)b * DIM + t + 256 * r] = smin[r] * invn;
}

// ---------------- launch ----------------
extern "C" void kernel_launch(void* const* d_in, const int* in_sizes, int n_in,
                              void* d_out, int out_size)
{
    const float* pos   = (const float*)d_in[0];
    const float* neg   = (const float*)d_in[1];
    const float* neut  = (const float*)d_in[2];
    const float* assas = (const float*)d_in[3];
    const float* vocab = (const float*)d_in[4];
    const float* W1 = (const float*)d_in[5];  const float* b1 = (const float*)d_in[6];
    const float* W2 = (const float*)d_in[7];  const float* b2 = (const float*)d_in[8];
    const float* W3 = (const float*)d_in[9];  const float* b3 = (const float*)d_in[10];
    const float* W4 = (const float*)d_in[11]; const float* b4 = (const float*)d_in[12];
    float* out = (float*)d_out;
    int NV = in_sizes[4] / DIM;

    float *p_x, *p_h1, *p_h2, *p_h3, *p_raw4, *p_model, *p_sims, *p_inv;
    cudaGetSymbolAddress((void**)&p_x,     g_x);
    cudaGetSymbolAddress((void**)&p_h1,    g_h1);
    cudaGetSymbolAddress((void**)&p_h2,    g_h2);
    cudaGetSymbolAddress((void**)&p_h3,    g_h3);
    cudaGetSymbolAddress((void**)&p_raw4,  g_raw4);
    cudaGetSymbolAddress((void**)&p_model, g_model);
    cudaGetSymbolAddress((void**)&p_sims,  g_sims);
    cudaGetSymbolAddress((void**)&p_inv,   g_inv_norm);

    vocab_norms<<<(NV + 7) / 8, 256>>>(vocab, NV);
    board_prep<<<BATCH, 256>>>(pos, neg, neut, assas);

    // MLP: 64x64 tiles (TM=TN=4), BK=32 -> grids of 144/108/64/48 CTAs
    gemm_f32x2<64, 64, 32, 4, 4, false><<<dim3((2304 + 63) / 64, 4), 256>>>(p_x,  W1, b1, p_h1,   BATCH, 2304, 3072, 1);
    gemm_f32x2<64, 64, 32, 4, 4, false><<<dim3((1700 + 63) / 64, 4), 256>>>(p_h1, W2, b2, p_h2,   BATCH, 1700, 2304, 1);
    gemm_f32x2<64, 64, 32, 4, 4, false><<<dim3((1000 + 63) / 64, 4), 256>>>(p_h2, W3, b3, p_h3,   BATCH, 1000, 1700, 1);
    gemm_f32x2<64, 64, 32, 4, 4, false><<<dim3(( 768 + 63) / 64, 4), 256>>>(p_h3, W4, b4, p_raw4, BATCH,  768, 1000, 0);

    norm_rows<<<BATCH, 256>>>(out);

    // sims: 128x128 tiles (TM=TN=8), BK=16
    gemm_f32x2<128, 128, 16, 8, 8, true><<<dim3((NV + 127) / 128, 2), 256>>>(p_model, vocab, p_inv, p_sims, BATCH, NV, DIM, 2);

    topk_kernel<<<BATCH, 256>>>(NV);
    gather_kernel<<<dim3(VTOP, BATCH), 256>>>(vocab, out);
    score_kernel<<<BATCH, 256>>>(out);
}

// round 11
// speedup vs baseline: 2.4411x; 1.3936x over previous
#include <cuda_runtime.h>
#include <cuda_bf16.h>
#include <math.h>
#include <stdint.h>

#define BATCH   256
#define DIM     768
#define NVOCAB  100000
#define VTOP    80
#define CAND    192           // approximate candidates kept before exact rescore
#define SEC     (BATCH*DIM)   // 196608 floats per output section

// ---------------- device scratch (static globals; no allocation) ----------------
__device__ float g_inv_norm[NVOCAB];
__device__ float g_x[BATCH*3072];
__device__ float g_h1[BATCH*2304];
__device__ float g_h2[BATCH*1700];
__device__ float g_h3[BATCH*1000];
__device__ float g_raw4[BATCH*DIM];
__device__ float g_model[BATCH*DIM];
__device__ float g_sims[BATCH*NVOCAB];          // ~102 MB (approximate sims)
__device__ int   g_topk[BATCH*VTOP];
__device__ float g_word[BATCH*VTOP*DIM];        // ~63 MB
__device__ float g_board[BATCH*26*DIM];         // ~20 MB
// bf16 of normalized vocab (B) and model_out (A)
__device__ __nv_bfloat16 g_vbh[(size_t)NVOCAB*DIM];   // ~154 MB
__device__ __nv_bfloat16 g_ahi[BATCH*DIM];

__device__ __forceinline__ float warp_sum(float v) {
#pragma unroll
    for (int o = 16; o; o >>= 1) v += __shfl_xor_sync(0xffffffffu, v, o);
    return v;
}

// ---- packed fp32 helpers (sm_100+ f32x2) ----
__device__ __forceinline__ unsigned long long pack2(float x, float y) {
    unsigned long long r;
    asm("mov.b64 %0, {%1, %2};" : "=l"(r) : "f"(x), "f"(y));
    return r;
}
__device__ __forceinline__ float2 unpack2(unsigned long long v) {
    float2 r;
    asm("mov.b64 {%0, %1}, %2;" : "=f"(r.x), "=f"(r.y) : "l"(v));
    return r;
}
__device__ __forceinline__ void fma2(unsigned long long& d, unsigned long long a, unsigned long long b) {
    asm("fma.rn.f32x2 %0, %1, %2, %3;" : "=l"(d) : "l"(a), "l"(b), "l"(d));
}

// ---- warp MMA helpers (baseline PTX, plain sm_103 target) ----
__device__ __forceinline__ uint32_t smem_to_u32(const void* smem_ptr) {
    uint32_t addr;
    asm("{ .reg .u64 tmp; cvta.to.shared.u64 tmp, %1; cvt.u32.u64 %0, tmp; }"
        : "=r"(addr) : "l"(smem_ptr));
    return addr;
}
__device__ __forceinline__ void ldsm_x4(uint32_t* r, uint32_t addr) {
    asm volatile("ldmatrix.sync.aligned.m8n8.x4.shared.b16 {%0,%1,%2,%3}, [%4];"
        : "=r"(r[0]), "=r"(r[1]), "=r"(r[2]), "=r"(r[3]) : "r"(addr));
}
__device__ __forceinline__ void mma16816(float* d, const uint32_t* a, const uint32_t* b) {
    asm volatile(
        "mma.sync.aligned.m16n8k16.row.col.f32.bf16.bf16.f32 "
        "{%0,%1,%2,%3}, {%4,%5,%6,%7}, {%8,%9}, {%0,%1,%2,%3};"
        : "+f"(d[0]), "+f"(d[1]), "+f"(d[2]), "+f"(d[3])
        : "r"(a[0]), "r"(a[1]), "r"(a[2]), "r"(a[3]), "r"(b[0]), "r"(b[1]));
}

// ---------------- vocab prep: inverse norms + bf16 of normalized vocab ----------------
__global__ __launch_bounds__(256) void vocab_prep(const float* __restrict__ vocab, int NV) {
    int row = blockIdx.x * 8 + (threadIdx.x >> 5);
    int lane = threadIdx.x & 31;
    if (row >= NV) return;
    const float* src = vocab + (size_t)row * DIM;
    float s = 0.f;
#pragma unroll 4
    for (int d = lane; d < DIM; d += 32) { float v = src[d]; s += v * v; }
    s = warp_sum(s);
    float inv = 1.0f / fmaxf(sqrtf(s), 1e-12f);
    if (lane == 0) g_inv_norm[row] = inv;
    size_t rb = (size_t)row * DIM;
#pragma unroll
    for (int step = 0; step < DIM / 64; step++) {
        int d = step * 64 + lane * 2;
        __nv_bfloat162 H;
        H.x = __float2bfloat16_rn(src[d] * inv);
        H.y = __float2bfloat16_rn(src[d + 1] * inv);
        *(__nv_bfloat162*)(g_vbh + rb + d) = H;
    }
}

// ---------------- board prep: normalized words + pooled MLP input ----------------
__global__ __launch_bounds__(256) void board_prep(
    const float* __restrict__ pos, const float* __restrict__ neg,
    const float* __restrict__ neut, const float* __restrict__ assas)
{
    int b = blockIdx.x;
    int t = threadIdx.x;
    int warp = t >> 5, lane = t & 31;

    for (int w = warp; w < 26; w += 8) {
        const float* src;
        if (w < 9)       src = pos  + ((size_t)b * 9 + w) * DIM;
        else if (w < 18) src = neg  + ((size_t)b * 9 + (w - 9)) * DIM;
        else if (w < 25) src = neut + ((size_t)b * 7 + (w - 18)) * DIM;
        else             src = assas + (size_t)b * DIM;
        float s = 0.f;
        for (int d = lane; d < DIM; d += 32) { float v = src[d]; s += v * v; }
        s = warp_sum(s);
        float inv = 1.0f / fmaxf(sqrtf(s), 1e-8f);
        float* dst = g_board + ((size_t)b * 26 + w) * DIM;
        for (int d = lane; d < DIM; d += 32) dst[d] = src[d] * inv;
    }

    __shared__ float red[256];
    float* xb = g_x + (size_t)b * 3072;

#pragma unroll
    for (int r = 0; r < 3; r++) {
        int d = t + 256 * r;
        xb[768 + d] = assas[(size_t)b * DIM + d];
    }

    const float* srcs[3] = { neg, neut, pos };
    const int nw[3] = { 9, 7, 9 };
    const int xoff[3] = { 0, 1536, 2304 };
    for (int g = 0; g < 3; g++) {
        float m[3];
#pragma unroll
        for (int r = 0; r < 3; r++) {
            int d = t + 256 * r;
            float s = 0.f;
            for (int w = 0; w < nw[g]; w++)
                s += srcs[g][((size_t)b * nw[g] + w) * DIM + d];
            m[r] = s / (float)nw[g];
        }
        red[t] = m[0]*m[0] + m[1]*m[1] + m[2]*m[2];
        __syncthreads();
        for (int s = 128; s > 0; s >>= 1) { if (t < s) red[t] += red[t + s]; __syncthreads(); }
        float inv = 1.0f / fmaxf(sqrtf(red[0]), 1e-12f);
        __syncthreads();
#pragma unroll
        for (int r = 0; r < 3; r++) xb[xoff[g] + t + 256 * r] = m[r] * inv;
    }
}

// ---------------- double-buffered f32x2 SGEMM for MLP ----------------
template<int BM, int BN, int BK, int TM, int TN, bool BT>
__global__ __launch_bounds__(256) void gemm_f32x2(
    const float* __restrict__ A, const float* __restrict__ B,
    const float* __restrict__ aux, float* __restrict__ C,
    int M, int N, int K, int mode)
{
    __shared__ float As[2][BK][BM];
    __shared__ float Bs[2][BK][BN];

    const int tid = threadIdx.x;
    const int m0 = blockIdx.y * BM, n0 = blockIdx.x * BN;
    const int NX = BN / TN;
    const int tx = tid % NX, ty = tid / NX;

    const int ACH = (BM * BK) / 1024;
    const int BCH = (BN * BK) / 1024;

    unsigned long long acc[TM][TN / 2];
#pragma unroll
    for (int i = 0; i < TM; i++)
#pragma unroll
        for (int j = 0; j < TN / 2; j++) acc[i][j] = 0ull;

    float4 ra[ACH], rb[BCH];
    const float4 z4 = make_float4(0.f, 0.f, 0.f, 0.f);

    auto load_tile = [&](int k0) {
#pragma unroll
        for (int c = 0; c < ACH; c++) {
            int li = tid + c * 256;
            int row = li / (BK / 4);
            int kc  = (li % (BK / 4)) * 4;
            int gm = m0 + row, gk = k0 + kc;
            ra[c] = (gm < M && gk < K) ? *(const float4*)(A + (size_t)gm * K + gk) : z4;
        }
        if (BT) {
#pragma unroll
            for (int c = 0; c < BCH; c++) {
                int li = tid + c * 256;
                int row = li / (BK / 4);
                int kc  = (li % (BK / 4)) * 4;
                int gn = n0 + row, gk = k0 + kc;
                rb[c] = (gn < N && gk < K) ? *(const float4*)(B + (size_t)gn * K + gk) : z4;
            }
        } else {
#pragma unroll
            for (int c = 0; c < BCH; c++) {
                int li = tid + c * 256;
                int krow = li / (BN / 4);
                int nc   = (li % (BN / 4)) * 4;
                int gk = k0 + krow, gn = n0 + nc;
                rb[c] = (gk < K && gn < N) ? *(const float4*)(B + (size_t)gk * N + gn) : z4;
            }
        }
    };
    auto store_tile = [&](int buf) {
#pragma unroll
        for (int c = 0; c < ACH; c++) {
            int li = tid + c * 256;
            int row = li / (BK / 4);
            int kc  = (li % (BK / 4)) * 4;
            As[buf][kc + 0][row] = ra[c].x;
            As[buf][kc + 1][row] = ra[c].y;
            As[buf][kc + 2][row] = ra[c].z;
            As[buf][kc + 3][row] = ra[c].w;
        }
        if (BT) {
#pragma unroll
            for (int c = 0; c < BCH; c++) {
                int li = tid + c * 256;
                int row = li / (BK / 4);
                int kc  = (li % (BK / 4)) * 4;
                Bs[buf][kc + 0][row] = rb[c].x;
                Bs[buf][kc + 1][row] = rb[c].y;
                Bs[buf][kc + 2][row] = rb[c].z;
                Bs[buf][kc + 3][row] = rb[c].w;
            }
        } else {
#pragma unroll
            for (int c = 0; c < BCH; c++) {
                int li = tid + c * 256;
                int krow = li / (BN / 4);
                int nc   = (li % (BN / 4)) * 4;
                *(float4*)&Bs[buf][krow][nc] = rb[c];
            }
        }
    };

    load_tile(0);
    store_tile(0);
    __syncthreads();

    int cur = 0;
    for (int k0 = 0; k0 < K; k0 += BK) {
        bool more = (k0 + BK) < K;
        if (more) load_tile(k0 + BK);

#pragma unroll
        for (int kk = 0; kk < BK; kk++) {
            float av[TM];
#pragma unroll
            for (int i = 0; i < TM; i += 4)
                *(float4*)&av[i] = *(const float4*)&As[cur][kk][ty * TM + i];
            unsigned long long aa[TM];
#pragma unroll
            for (int i = 0; i < TM; i++) aa[i] = pack2(av[i], av[i]);

            unsigned long long bb[TN / 2];
#pragma unroll
            for (int j = 0; j < TN; j += 4) {
                ulonglong2 tb = *(const ulonglong2*)&Bs[cur][kk][tx * TN + j];
                bb[j / 2]     = tb.x;
                bb[j / 2 + 1] = tb.y;
            }
#pragma unroll
            for (int i = 0; i < TM; i++)
#pragma unroll
                for (int j = 0; j < TN / 2; j++)
                    fma2(acc[i][j], aa[i], bb[j]);
        }

        if (more) {
            store_tile(cur ^ 1);
            __syncthreads();
            cur ^= 1;
        }
    }

#pragma unroll
    for (int i = 0; i < TM; i++) {
        int gm = m0 + ty * TM + i;
        if (gm >= M) continue;
#pragma unroll
        for (int j = 0; j < TN / 2; j++) {
            float2 v = unpack2(acc[i][j]);
            int gn = n0 + tx * TN + 2 * j;
            if (gn < N) {
                float o = v.x;
                if (mode == 2) o *= aux[gn];
                else { o += aux[gn]; if (mode == 1) o = fmaxf(o, 0.f); }
                C[(size_t)gm * N + gn] = o;
            }
            if (gn + 1 < N) {
                float o = v.y;
                if (mode == 2) o *= aux[gn + 1];
                else { o += aux[gn + 1]; if (mode == 1) o = fmaxf(o, 0.f); }
                C[(size_t)gm * N + gn + 1] = o;
            }
        }
    }
}

// ---------------- row L2 normalize -> g_model, out[sec0], bf16 A ----------------
__global__ __launch_bounds__(256) void norm_rows(float* __restrict__ out) {
    int b = blockIdx.x, t = threadIdx.x;
    __shared__ float red[256];
    const float* in = g_raw4 + (size_t)b * DIM;
    float v0 = in[t], v1 = in[t + 256], v2 = in[t + 512];
    red[t] = v0 * v0 + v1 * v1 + v2 * v2;
    __syncthreads();
    for (int s = 128; s > 0; s >>= 1) { if (t < s) red[t] += red[t + s]; __syncthreads(); }
    float inv = 1.0f / fmaxf(sqrtf(red[0]), 1e-12f);
    float* gm = g_model + (size_t)b * DIM;
    float* om = out + (size_t)b * DIM;
    float vals[3] = { v0 * inv, v1 * inv, v2 * inv };
#pragma unroll
    for (int r = 0; r < 3; r++) {
        int d = t + 256 * r;
        gm[d] = vals[r]; om[d] = vals[r];
        g_ahi[b * DIM + d] = __float2bfloat16_rn(vals[r]);
    }
}

// ---------------- approximate sims GEMM via mma.sync bf16 ----------------
// CTA tile 128m x 128n, BK=32, double-buffered smem, 8 warps (2x4 of 64m x 32n).
// smem per buffer: Ah@0, Bh@10240; row = 32 bf16 padded to 80 bytes.
#define SIMS_BUF_BYTES 20480
#define SIMS_SMEM      (2 * SIMS_BUF_BYTES)

__global__ __launch_bounds__(256) void sims_mma(int NV) {
    extern __shared__ char smem[];
    const uint32_t smem_u32 = smem_to_u32(smem);
    const int tid = threadIdx.x, wid = tid >> 5, lane = tid & 31;
    const int n0 = blockIdx.x * 128, m0 = blockIdx.y * 128;
    const int warp_m = wid >> 2, warp_n = wid & 3;

    float acc[4][4][4];
#pragma unroll
    for (int i = 0; i < 4; i++)
#pragma unroll
        for (int j = 0; j < 4; j++)
#pragma unroll
            for (int r = 0; r < 4; r++) acc[i][j][r] = 0.f;

    const uint4 z4 = make_uint4(0u, 0u, 0u, 0u);
    uint4 rah[2], rbh[2];

    auto load = [&](int k0) {
#pragma unroll
        for (int c = 0; c < 2; c++) {
            int li = tid + c * 256;
            int row = li >> 2, j = li & 3;
            rah[c] = *(const uint4*)(g_ahi + (size_t)(m0 + row) * DIM + k0 + j * 8);
            int gn = n0 + row;
            rbh[c] = (gn < NV) ? *(const uint4*)(g_vbh + (size_t)gn * DIM + k0 + j * 8) : z4;
        }
    };
    auto store = [&](int buf) {
        char* bb = smem + buf * SIMS_BUF_BYTES;
#pragma unroll
        for (int c = 0; c < 2; c++) {
            int li = tid + c * 256;
            int row = li >> 2, j = li & 3;
            int off = row * 80 + j * 16;
            *(uint4*)(bb + off)         = rah[c];
            *(uint4*)(bb + 10240 + off) = rbh[c];
        }
    };
    auto compute = [&](int buf) {
        uint32_t base = smem_u32 + buf * SIMS_BUF_BYTES;
        int a_row = warp_m * 64 + (lane & 15);
        int a_kb  = ((lane >> 4) * 8) * 2;
        int b_row = warp_n * 32 + (lane & 7) + ((lane >> 4) & 1) * 8;
        int b_kb  = (((lane >> 3) & 1) * 8) * 2;
#pragma unroll
        for (int kh = 0; kh < 2; kh++) {
            int kc2 = kh * 32;
            uint32_t ah[4][4], bh[2][4];
#pragma unroll
            for (int mi = 0; mi < 4; mi++)
                ldsm_x4(ah[mi], base + (uint32_t)((a_row + mi * 16) * 80 + a_kb + kc2));
#pragma unroll
            for (int p = 0; p < 2; p++)
                ldsm_x4(bh[p], base + 10240 + (uint32_t)((b_row + p * 16) * 80 + b_kb + kc2));
#pragma unroll
            for (int mi = 0; mi < 4; mi++)
#pragma unroll
                for (int ni = 0; ni < 4; ni++)
                    mma16816(acc[mi][ni], ah[mi], &bh[ni >> 1][(ni & 1) * 2]);
        }
    };

    load(0);
    store(0);
    __syncthreads();

    int cur = 0;
    for (int k0 = 0; k0 < DIM; k0 += 32) {
        bool more = (k0 + 32) < DIM;
        if (more) load(k0 + 32);
        compute(cur);
        if (more) {
            store(cur ^ 1);
            __syncthreads();
            cur ^= 1;
        }
    }

    int m_base = m0 + warp_m * 64;
    int n_base = n0 + warp_n * 32;
    int rr = lane >> 2, cc = (lane & 3) * 2;
#pragma unroll
    for (int mi = 0; mi < 4; mi++) {
#pragma unroll
        for (int ni = 0; ni < 4; ni++) {
            int n = n_base + ni * 8 + cc;
            if (n + 1 < NV) {
                int m = m_base + mi * 16 + rr;
                *(float2*)(g_sims + (size_t)m * NV + n) = make_float2(acc[mi][ni][0], acc[mi][ni][1]);
                *(float2*)(g_sims + (size_t)(m + 8) * NV + n) = make_float2(acc[mi][ni][2], acc[mi][ni][3]);
            } else if (n < NV) {
                int m = m_base + mi * 16 + rr;
                g_sims[(size_t)m * NV + n] = acc[mi][ni][0];
                g_sims[(size_t)(m + 8) * NV + n] = acc[mi][ni][2];
            }
        }
    }
}

// ---------------- top-80: approx candidate select -> exact fp32 rescore -> exact rank ----------------
__global__ __launch_bounds__(256) void topk_kernel(const float* __restrict__ vocab, int NV) {
    __shared__ unsigned int hist[2048];
    __shared__ float cval[2048];
    __shared__ int   cidx[2048];
    __shared__ int s_cnt, s_thr;
    int b = blockIdx.x, t = threadIdx.x;
    for (int i = t; i < 2048; i += 256) hist[i] = 0;
    if (t == 0) s_cnt = 0;
    __syncthreads();

    const float* row = g_sims + (size_t)b * NV;
    for (int n = t; n < NV; n += 256) {
        float v = row[n];
        int bin = (int)((v + 1.0f) * 1024.0f);
        bin = min(max(bin, 0), 2047);
        atomicAdd(&hist[bin], 1u);
    }
    __syncthreads();
    if (t == 0) {
        unsigned int c = 0; int bin = 2047;
        for (; bin >= 0; bin--) { c += hist[bin]; if (c >= CAND) break; }
        s_thr = bin;
    }
    __syncthreads();
    int thr = s_thr;
    for (int n = t; n < NV; n += 256) {
        float v = row[n];
        int bin = (int)((v + 1.0f) * 1024.0f);
        bin = min(max(bin, 0), 2047);
        if (bin >= thr) {
            int p = atomicAdd(&s_cnt, 1);
            if (p < 2048) cidx[p] = n;
        }
    }
    __syncthreads();
    int C = min(s_cnt, 2048);

    // exact fp32 rescore (sequential k order == passing fp32 GEMM; scale by inv_norm at end)
    const float* m = g_model + (size_t)b * DIM;
    for (int i = t; i < C; i += 256) {
        int idx = cidx[i];
        const float* v = vocab + (size_t)idx * DIM;
        float acc = 0.f;
#pragma unroll 8
        for (int k = 0; k < DIM; k++) acc = fmaf(m[k], v[k], acc);
        cval[i] = acc * g_inv_norm[idx];
    }
    __syncthreads();

    // exact rank with lax.top_k tie-break: value desc, index asc
    for (int i = t; i < C; i += 256) {
        float vi = cval[i]; int ii = cidx[i];
        int r = 0;
        for (int j = 0; j < C; j++) {
            float vj = cval[j];
            r += (vj > vi) || (vj == vi && cidx[j] < ii);
        }
        if (r < VTOP) g_topk[b * VTOP + r] = ii;
    }
}

// ---------------- gather normalized word embeddings; write out[sec1] for v==0 ----------------
__global__ __launch_bounds__(256) void gather_kernel(const float* __restrict__ vocab, float* __restrict__ out) {
    int v = blockIdx.x, b = blockIdx.y, t = threadIdx.x;
    int idx = g_topk[b * VTOP + v];
    float inv = g_inv_norm[idx];
    const float* src = vocab + (size_t)idx * DIM;
    float* dst = g_word + ((size_t)b * VTOP + v) * DIM;
    for (int d = t; d < DIM; d += 256) {
        float val = src[d] * inv;
        dst[d] = val;
        if (v == 0) out[SEC + (size_t)b * DIM + d] = val;
    }
}

// ---------------- scoring + reward + selection + pooling ----------------
__global__ __launch_bounds__(256) void score_kernel(float* __restrict__ out) {
    int b = blockIdx.x, t = threadIdx.x;
    int warp = t >> 5, lane = t & 31;
    __shared__ float S[VTOP][26];
    __shared__ float tot[VTOP];
    __shared__ unsigned char inmax[VTOP], inmin[VTOP];
    __shared__ float red[256];

    for (int v = warp; v < VTOP; v += 8) {
        if (lane < 26) {
            const float4* w = (const float4*)(g_word + ((size_t)b * VTOP + v) * DIM);
            const float4* brd = (const float4*)(g_board + ((size_t)b * 26 + lane) * DIM);
            float acc = 0.f;
#pragma unroll 8
            for (int d = 0; d < DIM / 4; d++) {
                float4 a = w[d], c = brd[d];
                acc += a.x * c.x + a.y * c.y + a.z * c.z + a.w * c.w;
            }
            S[v][lane] = acc;
        }
    }
    __syncthreads();

    if (t < VTOP) {
        float maxbad = -1e30f;
#pragma unroll
        for (int j = 9; j < 26; j++) maxbad = fmaxf(maxbad, S[t][j]);
        int nc = 0;
#pragma unroll
        for (int j = 0; j < 9; j++) nc += (S[t][j] >= maxbad) ? 1 : 0;
        int jm = 25;
        for (int j = 9; j < 26; j++) { if (S[t][j] == maxbad) { jm = j; break; } }
        float sec = (jm <= 17) ? 0.0f : ((jm <= 24) ? 1.0f : -10.0f);
        tot[t] = (float)nc + sec;
    }
    __syncthreads();

    if (t < VTOP) {
        float tv = tot[t];
        int rmax = 0, rmin = 0;
        for (int u = 0; u < VTOP; u++) {
            float tu = tot[u];
            rmax += (tu > tv) || (tu == tv && u < t);
            rmin += (tu < tv) || (tu == tv && u < t);
        }
        inmax[t] = (rmax < VTOP / 2);
        inmin[t] = (rmin < VTOP / 2);
    }
    __syncthreads();

    float smax[3] = {0.f, 0.f, 0.f}, smin[3] = {0.f, 0.f, 0.f};
    for (int v = 0; v < VTOP; v++) {
        const float* w = g_word + ((size_t)b * VTOP + v) * DIM;
        bool fx = inmax[v], fn = inmin[v];
#pragma unroll
        for (int r = 0; r < 3; r++) {
            float val = w[t + 256 * r];
            if (fx) smax[r] += val;
            if (fn) smin[r] += val;
        }
    }
#pragma unroll
    for (int r = 0; r < 3; r++) { smax[r] *= (1.0f / 40.0f); smin[r] *= (1.0f / 40.0f); }

    red[t] = smax[0]*smax[0] + smax[1]*smax[1] + smax[2]*smax[2];
    __syncthreads();
    for (int s = 128; s > 0; s >>= 1) { if (t < s) red[t] += red[t + s]; __syncthreads(); }
    float invx = 1.0f / fmaxf(sqrtf(red[0]), 1e-12f);
    __syncthreads();
#pragma unroll
    for (int r = 0; r < 3; r++) out[2 * SEC + (size_t)b * DIM + t + 256 * r] = smax[r] * invx;

    red[t] = smin[0]*smin[0] + smin[1]*smin[1] + smin[2]*smin[2];
    __syncthreads();
    for (int s = 128; s > 0; s >>= 1) { if (t < s) red[t] += red[t + s]; __syncthreads(); }
    float invn = 1.0f / fmaxf(sqrtf(red[0]), 1e-12f);
    __syncthreads();
#pragma unroll
    for (int r = 0; r < 3; r++) out[3 * SEC + (size_t)b * DIM + t + 256 * r] = smin[r] * invn;
}

// ---------------- launch ----------------
extern "C" void kernel_launch(void* const* d_in, const int* in_sizes, int n_in,
                              void* d_out, int out_size)
{
    const float* pos   = (const float*)d_in[0];
    const float* neg   = (const float*)d_in[1];
    const float* neut  = (const float*)d_in[2];
    const float* assas = (const float*)d_in[3];
    const float* vocab = (const float*)d_in[4];
    const float* W1 = (const float*)d_in[5];  const float* b1 = (const float*)d_in[6];
    const float* W2 = (const float*)d_in[7];  const float* b2 = (const float*)d_in[8];
    const float* W3 = (const float*)d_in[9];  const float* b3 = (const float*)d_in[10];
    const float* W4 = (const float*)d_in[11]; const float* b4 = (const float*)d_in[12];
    float* out = (float*)d_out;
    int NV = in_sizes[4] / DIM;

    float *p_x, *p_h1, *p_h2, *p_h3, *p_raw4;
    cudaGetSymbolAddress((void**)&p_x,     g_x);
    cudaGetSymbolAddress((void**)&p_h1,    g_h1);
    cudaGetSymbolAddress((void**)&p_h2,    g_h2);
    cudaGetSymbolAddress((void**)&p_h3,    g_h3);
    cudaGetSymbolAddress((void**)&p_raw4,  g_raw4);

    cudaFuncSetAttribute(sims_mma, cudaFuncAttributeMaxDynamicSharedMemorySize, SIMS_SMEM);

    vocab_prep<<<(NV + 7) / 8, 256>>>(vocab, NV);
    board_prep<<<BATCH, 256>>>(pos, neg, neut, assas);

    gemm_f32x2<64, 64, 32, 4, 4, false><<<dim3((2304 + 63) / 64, 4), 256>>>(p_x,  W1, b1, p_h1,   BATCH, 2304, 3072, 1);
    gemm_f32x2<64, 64, 32, 4, 4, false><<<dim3((1700 + 63) / 64, 4), 256>>>(p_h1, W2, b2, p_h2,   BATCH, 1700, 2304, 1);
    gemm_f32x2<64, 64, 32, 4, 4, false><<<dim3((1000 + 63) / 64, 4), 256>>>(p_h2, W3, b3, p_h3,   BATCH, 1000, 1700, 1);
    gemm_f32x2<64, 64, 32, 4, 4, false><<<dim3(( 768 + 63) / 64, 4), 256>>>(p_h3, W4, b4, p_raw4, BATCH,  768, 1000, 0);

    norm_rows<<<BATCH, 256>>>(out);

    sims_mma<<<dim3((NV + 127) / 128, 2), 256, SIMS_SMEM>>>(NV);

    topk_kernel<<<BATCH, 256>>>(vocab, NV);
    gather_kernel<<<dim3(VTOP, BATCH), 256>>>(vocab, out);
    score_kernel<<<BATCH, 256>>>(out);
}